// round 4
// baseline (speedup 1.0000x reference)
#include <cuda_runtime.h>

#define NN 4096
#define BB 8
#define NBTOT (BB*NN)

typedef unsigned long long u64;

__device__ __forceinline__ u64 dup2(float x) {
    u64 r; asm("mov.b64 %0, {%1, %1};" : "=l"(r) : "f"(x)); return r;
}
__device__ __forceinline__ float2 unpk(u64 v) {
    float2 r; asm("mov.b64 {%0, %1}, %2;" : "=f"(r.x), "=f"(r.y) : "l"(v)); return r;
}
__device__ __forceinline__ void ffma2(u64& acc, u64 a, u64 b) {
    asm("fma.rn.f32x2 %0, %1, %2, %0;" : "+l"(acc) : "l"(a), "l"(b));
}

// ------------- scratch: one big device global (no allocations) -------------
#define BUF 2097152  // BB*64*NN
__device__ float SCR[8*BUF + 2*BB*NN + 256 + 5*128 + 1024];

// stats slot layout: stat[c] = sum, stat[64+c] = sumsq
__device__ __forceinline__ void bn_coef(const float* __restrict__ stat,
                                        const float* __restrict__ g,
                                        const float* __restrict__ be,
                                        int c, float& sc, float& sh) {
    const float inv = 1.0f / (float)NBTOT;
    float mean = stat[c] * inv;
    float var  = stat[64 + c] * inv - mean * mean;
    float r = rsqrtf(var + 1e-5f);
    sc = g[c] * r;
    sh = be[c] - sc * mean;
}

// stage 1: per-(c,b) sum & sumsq; grid (C, BB)
__global__ void k_stats1(const float* __restrict__ d, int C, float* __restrict__ st2) {
    int c = blockIdx.x, b = blockIdx.y;
    const float* p = d + (b * C + c) * NN;
    float s = 0.f, sq = 0.f;
    for (int i = threadIdx.x; i < NN; i += 256) {
        float v = p[i];
        s += v; sq += v * v;
    }
    __shared__ float shs[8], shq[8];
    for (int o = 16; o; o >>= 1) {
        s  += __shfl_down_sync(0xffffffffu, s, o);
        sq += __shfl_down_sync(0xffffffffu, sq, o);
    }
    if ((threadIdx.x & 31) == 0) { shs[threadIdx.x >> 5] = s; shq[threadIdx.x >> 5] = sq; }
    __syncthreads();
    if (threadIdx.x == 0) {
        float S = 0.f, Q = 0.f;
        #pragma unroll
        for (int i = 0; i < 8; i++) { S += shs[i]; Q += shq[i]; }
        st2[b * 128 + c] = S; st2[b * 128 + 64 + c] = Q;
    }
}
// stage 2: reduce over b in fixed order; 1 block, 64 threads
__global__ void k_stats2(const float* __restrict__ st2, int C, float* __restrict__ stat) {
    int t = threadIdx.x;
    if (t < C) {
        float S = 0.f, Q = 0.f;
        #pragma unroll
        for (int b = 0; b < BB; b++) { S += st2[b * 128 + t]; Q += st2[b * 128 + 64 + t]; }
        stat[t] = S; stat[64 + t] = Q;
    }
}

// stem conv: x[8,6,N] -> y[8,32,N]
__global__ void k_conv1(const float* __restrict__ x, const float* __restrict__ w,
                        const float* __restrict__ bias, float* __restrict__ y) {
    __shared__ float ws[192], bs[32];
    int t = threadIdx.x;
    if (t < 192) ws[t] = w[t];
    if (t < 32)  bs[t] = bias[t];
    __syncthreads();
    int b = blockIdx.y, n = blockIdx.x * 256 + t;
    float in[6];
    #pragma unroll
    for (int c = 0; c < 6; c++) in[c] = x[(b * 6 + c) * NN + n];
    #pragma unroll
    for (int o = 0; o < 32; o++) {
        float a = bs[o];
        #pragma unroll
        for (int c = 0; c < 6; c++) a = fmaf(ws[o * 6 + c], in[c], a);
        y[(b * 32 + o) * NN + n] = a;
    }
}

// BN(stats)+relu then 32x32 conv
__global__ void k_bnconv32(const float* __restrict__ yin, const float* __restrict__ stat,
                           const float* __restrict__ g, const float* __restrict__ be,
                           const float* __restrict__ w, const float* __restrict__ bias,
                           float* __restrict__ yout) {
    __shared__ float ws[1024], bs[32], sc[32], sh[32];
    int t = threadIdx.x;
    for (int i = t; i < 1024; i += 256) ws[i] = w[i];
    if (t < 32) { bs[t] = bias[t]; bn_coef(stat, g, be, t, sc[t], sh[t]); }
    __syncthreads();
    int b = blockIdx.y, n = blockIdx.x * 256 + t;
    float in[32];
    #pragma unroll
    for (int c = 0; c < 32; c++)
        in[c] = fmaxf(fmaf(sc[c], yin[(b * 32 + c) * NN + n], sh[c]), 0.f);
    for (int o = 0; o < 32; o++) {
        float a = bs[o];
        #pragma unroll
        for (int c = 0; c < 32; c++) a = fmaf(ws[o * 32 + c], in[c], a);
        yout[(b * 32 + o) * NN + n] = a;
    }
}

// BN+relu -> h; qk = wqk@h; v = wv@h + bv
template<int C>
__global__ void k_bnqkv(const float* __restrict__ yin, const float* __restrict__ stat,
                        const float* __restrict__ g, const float* __restrict__ be,
                        const float* __restrict__ wqk, const float* __restrict__ wv,
                        const float* __restrict__ bv,
                        float* __restrict__ h, float* __restrict__ qk, float* __restrict__ v) {
    __shared__ float wq_s[C*C], wv_s[C*C], bvs[C], sc[C], sh[C];
    int t = threadIdx.x;
    for (int i = t; i < C*C; i += 256) { wq_s[i] = wqk[i]; wv_s[i] = wv[i]; }
    if (t < C) { bvs[t] = bv[t]; bn_coef(stat, g, be, t, sc[t], sh[t]); }
    __syncthreads();
    int b = blockIdx.y, n = blockIdx.x * 256 + t;
    float in[C];
    #pragma unroll
    for (int c = 0; c < C; c++) {
        float val = fmaxf(fmaf(sc[c], yin[(b * C + c) * NN + n], sh[c]), 0.f);
        in[c] = val;
        h[(b * C + c) * NN + n] = val;
    }
    for (int o = 0; o < C; o++) {
        float aq = 0.f, av = bvs[o];
        #pragma unroll
        for (int c = 0; c < C; c++) {
            aq = fmaf(wq_s[o * C + c], in[c], aq);
            av = fmaf(wv_s[o * C + c], in[c], av);
        }
        qk[(b * C + o) * NN + n] = aq;
        v [(b * C + o) * NN + n] = av;
    }
}

// ---------------- attention pass A: per-row max + sumexp ----------------
// grid (NN/128, BB), 256 thr. A tile (n-block) persistent; B tiles streamed.
// FFMA2 inner loop, 8x8 microtile per thread (acc packed over m-dim).
template<int C>
__global__ void k_attA(const float* __restrict__ qk, float* __restrict__ Mr,
                       float* __restrict__ iL) {
    extern __shared__ float dsm[];
    float* As = dsm;            // C*128
    float* Bs = dsm + C * 128;  // C*128
    __shared__ float RM[128][17], RL[128][17];
    const int b = blockIdx.y, n0 = blockIdx.x * 128, t = threadIdx.x;
    const int rowg = t >> 4, colg = t & 15;

    for (int idx = t; idx < C * 128; idx += 256) {
        int k = idx >> 7, i = idx & 127;
        As[idx] = qk[(b * C + k) * NN + n0 + i];
    }

    float Mloc[8], Lloc[8];
    #pragma unroll
    for (int i = 0; i < 8; i++) { Mloc[i] = -1e30f; Lloc[i] = 0.f; }

    for (int mt = 0; mt < NN / 128; mt++) {
        const int m0 = mt * 128;
        __syncthreads();
        for (int idx = t; idx < C * 128; idx += 256) {
            int k = idx >> 7, i = idx & 127;
            Bs[idx] = qk[(b * C + k) * NN + m0 + i];
        }
        __syncthreads();
        u64 acc[8][4];
        #pragma unroll
        for (int i = 0; i < 8; i++)
            #pragma unroll
            for (int j = 0; j < 4; j++) acc[i][j] = 0ULL;
        #pragma unroll 4
        for (int k = 0; k < C; k++) {
            float4 a0 = *(float4*)&As[k * 128 + rowg * 8];
            float4 a1 = *(float4*)&As[k * 128 + rowg * 8 + 4];
            ulonglong2 b0 = *(ulonglong2*)&Bs[k * 128 + colg * 8];
            ulonglong2 b1 = *(ulonglong2*)&Bs[k * 128 + colg * 8 + 4];
            float a[8] = {a0.x, a0.y, a0.z, a0.w, a1.x, a1.y, a1.z, a1.w};
            u64 bp[4] = {b0.x, b0.y, b1.x, b1.y};
            #pragma unroll
            for (int i = 0; i < 8; i++) {
                u64 ad = dup2(a[i]);
                #pragma unroll
                for (int j = 0; j < 4; j++) ffma2(acc[i][j], ad, bp[j]);
            }
        }
        // online softmax update (rows = n-dim, cols = m-dim)
        #pragma unroll
        for (int i = 0; i < 8; i++) {
            float s[8];
            #pragma unroll
            for (int j = 0; j < 4; j++) {
                float2 p = unpk(acc[i][j]);
                s[2 * j] = p.x; s[2 * j + 1] = p.y;
            }
            float tmax = s[0];
            #pragma unroll
            for (int j = 1; j < 8; j++) tmax = fmaxf(tmax, s[j]);
            float Mn = fmaxf(Mloc[i], tmax);
            float l = Lloc[i] * __expf(Mloc[i] - Mn);
            #pragma unroll
            for (int j = 0; j < 8; j++) l += __expf(s[j] - Mn);
            Mloc[i] = Mn; Lloc[i] = l;
        }
    }
    __syncthreads();
    #pragma unroll
    for (int i = 0; i < 8; i++) {
        RM[rowg * 8 + i][colg] = Mloc[i];
        RL[rowg * 8 + i][colg] = Lloc[i];
    }
    __syncthreads();
    if (t < 128) {
        float M = -1e30f, L = 0.f;
        #pragma unroll
        for (int p = 0; p < 16; p++) {
            float m2 = RM[t][p], l2 = RL[t][p];
            float Mn = fmaxf(M, m2);
            L = L * __expf(M - Mn) + l2 * __expf(m2 - Mn);
            M = Mn;
        }
        Mr[b * NN + n0 + t] = M;
        iL[b * NN + n0 + t] = 1.0f / L;
    }
}

// ---------------- attention pass B: column sums + V*attn + renorm ----------------
// grid (NN/128 col-tiles, BB), 256 thr, dynamic smem. FFMA2 everywhere.
template<int C>
__global__ void k_attB(const float* __restrict__ qk, const float* __restrict__ v,
                       const float* __restrict__ Mr, const float* __restrict__ iLp,
                       float* __restrict__ xr) {
    constexpr int VS = C + 2;      // padded V-transpose stride
    constexpr int NP = C / 16;     // channel pairs per thread
    extern __shared__ float dsm[];
    float* Qm   = dsm;               // C*128
    float* Qn   = Qm + C * 128;      // C*32
    float* VsT  = Qn + C * 32;       // 32*VS   (VsT[i*VS + c])
    float* Es   = VsT + 32 * VS;     // 32*132
    float* sred = Es + 32 * 132;     // 256
    float* sinv = sred + 256;        // 128
    __shared__ float Ms[32], Ls[32];

    const int b = blockIdx.y, m0 = blockIdx.x * 128, t = threadIdx.x;
    for (int idx = t; idx < C * 128; idx += 256) {
        int k = idx >> 7, j = idx & 127;
        Qm[k * 128 + j] = qk[(b * C + k) * NN + m0 + j];
    }
    const int i0 = (t >> 5) * 4;       // S rows (n-dim within tile)
    const int j0 = (t & 31) * 4;       // S / u cols (m-dim)
    const int c0 = (t >> 5) * (C / 8); // u channel base
    const int jjs = t & 127, hf = t >> 7;

    u64 u2[NP][4];
    #pragma unroll
    for (int ci = 0; ci < NP; ci++)
        #pragma unroll
        for (int j = 0; j < 4; j++) u2[ci][j] = 0ULL;
    float sacc = 0.f;

    for (int nt = 0; nt < NN / 32; nt++) {
        const int n0 = nt * 32;
        __syncthreads();
        for (int idx = t; idx < C * 32; idx += 256) {
            int k = idx >> 5, i = idx & 31;
            Qn[idx] = qk[(b * C + k) * NN + n0 + i];
            VsT[i * VS + k] = v[(b * C + k) * NN + n0 + i];
        }
        if (t < 32) { Ms[t] = Mr[b * NN + n0 + t]; Ls[t] = iLp[b * NN + n0 + t]; }
        __syncthreads();

        u64 s2[4][2];
        #pragma unroll
        for (int i = 0; i < 4; i++) { s2[i][0] = 0ULL; s2[i][1] = 0ULL; }
        #pragma unroll 8
        for (int k = 0; k < C; k++) {
            float4 av = *(float4*)&Qn[k * 32 + i0];
            ulonglong2 bv = *(ulonglong2*)&Qm[k * 128 + j0];
            float a[4] = {av.x, av.y, av.z, av.w};
            #pragma unroll
            for (int i = 0; i < 4; i++) {
                u64 ad = dup2(a[i]);
                ffma2(s2[i][0], ad, bv.x);
                ffma2(s2[i][1], ad, bv.y);
            }
        }
        #pragma unroll
        for (int ii = 0; ii < 4; ii++) {
            float m = Ms[i0 + ii], il = Ls[i0 + ii];
            float2 p0 = unpk(s2[ii][0]), p1 = unpk(s2[ii][1]);
            float4 ev;
            ev.x = __expf(p0.x - m) * il;
            ev.y = __expf(p0.y - m) * il;
            ev.z = __expf(p1.x - m) * il;
            ev.w = __expf(p1.y - m) * il;
            *(float4*)&Es[(i0 + ii) * 132 + j0] = ev;
        }
        __syncthreads();
        #pragma unroll
        for (int i = 0; i < 16; i++) sacc += Es[(hf * 16 + i) * 132 + jjs];
        #pragma unroll 8
        for (int i = 0; i < 32; i++) {
            float4 ev4 = *(float4*)&Es[i * 132 + j0];
            u64 ed[4] = {dup2(ev4.x), dup2(ev4.y), dup2(ev4.z), dup2(ev4.w)};
            #pragma unroll
            for (int ci = 0; ci < NP; ci++) {
                u64 vp = *(u64*)&VsT[i * VS + c0 + 2 * ci];
                #pragma unroll
                for (int j = 0; j < 4; j++) ffma2(u2[ci][j], vp, ed[j]);
            }
        }
    }
    __syncthreads();
    sred[t] = sacc;
    __syncthreads();
    if (t < 128) sinv[t] = 1.0f / (1e-9f + sred[t] + sred[t + 128]);
    __syncthreads();
    #pragma unroll
    for (int ci = 0; ci < NP; ci++)
        #pragma unroll
        for (int j = 0; j < 4; j++) {
            float2 uu = unpk(u2[ci][j]);
            float si = sinv[j0 + j];
            int col = m0 + j0 + j;
            xr[(b * C + c0 + 2 * ci)     * NN + col] = uu.x * si;
            xr[(b * C + c0 + 2 * ci + 1) * NN + col] = uu.y * si;
        }
}

// tp = wt @ (h - xr) + bt
template<int C>
__global__ void k_diffconv(const float* __restrict__ h, const float* __restrict__ xr,
                           const float* __restrict__ wt, const float* __restrict__ bt,
                           float* __restrict__ tp) {
    __shared__ float ws[C*C], bs[C];
    int t = threadIdx.x;
    for (int i = t; i < C*C; i += 256) ws[i] = wt[i];
    if (t < C) bs[t] = bt[t];
    __syncthreads();
    int b = blockIdx.y, n = blockIdx.x * 256 + t;
    float din[C];
    #pragma unroll
    for (int c = 0; c < C; c++)
        din[c] = h[(b * C + c) * NN + n] - xr[(b * C + c) * NN + n];
    for (int o = 0; o < C; o++) {
        float a = bs[o];
        #pragma unroll
        for (int c = 0; c < C; c++) a = fmaf(ws[o * C + c], din[c], a);
        tp[(b * C + o) * NN + n] = a;
    }
}

// out = h + relu(BN(tp))
template<int C>
__global__ void k_resid(const float* __restrict__ h, const float* __restrict__ tp,
                        const float* __restrict__ stat, const float* __restrict__ g,
                        const float* __restrict__ be, float* __restrict__ out) {
    int idx = blockIdx.x * 256 + threadIdx.x;
    int c = (idx >> 12) & (C - 1);
    float sc, sh;
    bn_coef(stat, g, be, c, sc, sh);
    float tv = fmaf(sc, tp[idx], sh);
    out[idx] = h[idx] + fmaxf(tv, 0.f);
}

// per-(b,c) max over N
__global__ void k_max(const float* __restrict__ d, float* __restrict__ gf) {
    int bc = blockIdx.x;
    const float* p = d + bc * NN;
    float m = -1e30f;
    for (int i = threadIdx.x; i < NN; i += 256) m = fmaxf(m, p[i]);
    __shared__ float sm_[8];
    for (int o = 16; o; o >>= 1) m = fmaxf(m, __shfl_down_sync(0xffffffffu, m, o));
    if ((threadIdx.x & 31) == 0) sm_[threadIdx.x >> 5] = m;
    __syncthreads();
    if (threadIdx.x == 0) {
        float M = sm_[0];
        #pragma unroll
        for (int i = 1; i < 8; i++) M = fmaxf(M, sm_[i]);
        gf[bc] = M;
    }
}

// y3 = w3 @ concat(h3, broadcast gf1) + b3
__global__ void k_concatconv(const float* __restrict__ h3, const float* __restrict__ gf1,
                             const float* __restrict__ w3, const float* __restrict__ b3,
                             float* __restrict__ y3) {
    __shared__ float ws[4096], K[64];
    int t = threadIdx.x, b = blockIdx.y;
    for (int i = t; i < 4096; i += 256) ws[i] = w3[i];
    __syncthreads();
    if (t < 64) {
        float a = b3[t];
        #pragma unroll
        for (int c = 0; c < 32; c++) a = fmaf(ws[t * 64 + 32 + c], gf1[b * 32 + c], a);
        K[t] = a;
    }
    __syncthreads();
    int n = blockIdx.x * 256 + t;
    float in[32];
    #pragma unroll
    for (int c = 0; c < 32; c++) in[c] = h3[(b * 32 + c) * NN + n];
    for (int o = 0; o < 64; o++) {
        float a = K[o];
        #pragma unroll
        for (int c = 0; c < 32; c++) a = fmaf(ws[o * 64 + c], in[c], a);
        y3[(b * 64 + o) * NN + n] = a;
    }
}

extern "C" void kernel_launch(void* const* d_in, const int* in_sizes, int n_in,
                              void* d_out, int out_size) {
    const float* x      = (const float*)d_in[0];
    const float* w1     = (const float*)d_in[1];
    const float* b1     = (const float*)d_in[2];
    const float* g1     = (const float*)d_in[3];
    const float* be1    = (const float*)d_in[4];
    const float* w2     = (const float*)d_in[5];
    const float* b2     = (const float*)d_in[6];
    const float* g2     = (const float*)d_in[7];
    const float* be2    = (const float*)d_in[8];
    const float* a1_wqk = (const float*)d_in[9];
    const float* a1_wv  = (const float*)d_in[10];
    const float* a1_bv  = (const float*)d_in[11];
    const float* a1_wt  = (const float*)d_in[12];
    const float* a1_bt  = (const float*)d_in[13];
    const float* a1_g   = (const float*)d_in[14];
    const float* a1_b   = (const float*)d_in[15];
    const float* w3     = (const float*)d_in[16];
    const float* b3     = (const float*)d_in[17];
    const float* g3     = (const float*)d_in[18];
    const float* be3    = (const float*)d_in[19];
    const float* a2_wqk = (const float*)d_in[20];
    const float* a2_wv  = (const float*)d_in[21];
    const float* a2_bv  = (const float*)d_in[22];
    const float* a2_wt  = (const float*)d_in[23];
    const float* a2_bt  = (const float*)d_in[24];
    const float* a2_g   = (const float*)d_in[25];
    const float* a2_b   = (const float*)d_in[26];

    float* S = nullptr;
    cudaGetSymbolAddress((void**)&S, SCR);
    float* y1  = S + 0 * BUF;   // also h4 (layer2)
    float* y2  = S + 1 * BUF;   // also y3
    float* h2  = S + 2 * BUF;
    float* qkb = S + 3 * BUF;
    float* vb  = S + 4 * BUF;
    float* xrb = S + 5 * BUF;
    float* tpb = S + 6 * BUF;
    float* h3  = S + 7 * BUF;
    float* Mr  = S + 8 * BUF;
    float* iL  = Mr + BB * NN;
    float* gf1 = iL + BB * NN;
    float* st  = gf1 + 256;     // 5 slots of 128
    float* st2 = st + 5 * 128;  // 1024 partials

    float* outh  = (float*)d_out;
    float* outgf = outh + BB * 64 * NN;

    int smA32 = 32 * 128 * 2 * 4;
    int smA64 = 64 * 128 * 2 * 4;
    int smB32 = (32 * 128 + 32 * 32 + 32 * (32 + 2) + 32 * 132 + 256 + 128) * 4;
    int smB64 = (64 * 128 + 64 * 32 + 32 * (64 + 2) + 32 * 132 + 256 + 128) * 4;
    cudaFuncSetAttribute(k_attA<32>, cudaFuncAttributeMaxDynamicSharedMemorySize, smA32);
    cudaFuncSetAttribute(k_attA<64>, cudaFuncAttributeMaxDynamicSharedMemorySize, smA64);
    cudaFuncSetAttribute(k_attB<32>, cudaFuncAttributeMaxDynamicSharedMemorySize, smB32);
    cudaFuncSetAttribute(k_attB<64>, cudaFuncAttributeMaxDynamicSharedMemorySize, smB64);

    dim3 gN(NN / 256, BB), gA(NN / 128, BB);

    // stem
    k_conv1<<<gN, 256>>>(x, w1, b1, y1);
    k_stats1<<<dim3(32, BB), 256>>>(y1, 32, st2);
    k_stats2<<<1, 64>>>(st2, 32, st + 0 * 128);
    k_bnconv32<<<gN, 256>>>(y1, st + 0 * 128, g1, be1, w2, b2, y2);
    k_stats1<<<dim3(32, BB), 256>>>(y2, 32, st2);
    k_stats2<<<1, 64>>>(st2, 32, st + 1 * 128);
    // att1 (C=32)
    k_bnqkv<32><<<gN, 256>>>(y2, st + 1 * 128, g2, be2, a1_wqk, a1_wv, a1_bv, h2, qkb, vb);
    k_attA<32><<<gA, 256, smA32>>>(qkb, Mr, iL);
    k_attB<32><<<gA, 256, smB32>>>(qkb, vb, Mr, iL, xrb);
    k_diffconv<32><<<gN, 256>>>(h2, xrb, a1_wt, a1_bt, tpb);
    k_stats1<<<dim3(32, BB), 256>>>(tpb, 32, st2);
    k_stats2<<<1, 64>>>(st2, 32, st + 2 * 128);
    k_resid<32><<<BB * 32 * NN / 256, 256>>>(h2, tpb, st + 2 * 128, a1_g, a1_b, h3);
    k_max<<<BB * 32, 256>>>(h3, gf1);
    // concat + conv3
    k_concatconv<<<gN, 256>>>(h3, gf1, w3, b3, y2);
    k_stats1<<<dim3(64, BB), 256>>>(y2, 64, st2);
    k_stats2<<<1, 64>>>(st2, 64, st + 3 * 128);
    // att2 (C=64)
    k_bnqkv<64><<<gN, 256>>>(y2, st + 3 * 128, g3, be3, a2_wqk, a2_wv, a2_bv, y1, qkb, vb);
    k_attA<64><<<gA, 256, smA64>>>(qkb, Mr, iL);
    k_attB<64><<<gA, 256, smB64>>>(qkb, vb, Mr, iL, xrb);
    k_diffconv<64><<<gN, 256>>>(y1, xrb, a2_wt, a2_bt, tpb);
    k_stats1<<<dim3(64, BB), 256>>>(tpb, 64, st2);
    k_stats2<<<1, 64>>>(st2, 64, st + 4 * 128);
    k_resid<64><<<BB * 64 * NN / 256, 256>>>(y1, tpb, st + 4 * 128, a2_g, a2_b, outh);
    k_max<<<BB * 64, 256>>>(outh, outgf);
}

// round 6
// speedup vs baseline: 1.0584x; 1.0584x over previous
#include <cuda_runtime.h>
#include <cstdint>

#define NN 4096
#define BB 8
#define NBTOT (BB*NN)

__device__ __forceinline__ float tf32r(float x) {
    uint32_t r; asm("cvt.rna.tf32.f32 %0, %1;" : "=r"(r) : "f"(x)); return __uint_as_float(r);
}
__device__ __forceinline__ void mma8(float* d, const uint32_t* a, uint32_t b0, uint32_t b1) {
    asm volatile("mma.sync.aligned.m16n8k8.row.col.f32.tf32.tf32.f32 "
        "{%0,%1,%2,%3}, {%4,%5,%6,%7}, {%8,%9}, {%0,%1,%2,%3};"
        : "+f"(d[0]), "+f"(d[1]), "+f"(d[2]), "+f"(d[3])
        : "r"(a[0]), "r"(a[1]), "r"(a[2]), "r"(a[3]), "r"(b0), "r"(b1));
}
__device__ __forceinline__ void ldfragA(uint32_t* f, const float* base, int stride, int rb, int kb, int r, int q) {
    f[0] = __float_as_uint(base[(rb + r) * stride + kb + q]);
    f[1] = __float_as_uint(base[(rb + r + 8) * stride + kb + q]);
    f[2] = __float_as_uint(base[(rb + r) * stride + kb + q + 4]);
    f[3] = __float_as_uint(base[(rb + r + 8) * stride + kb + q + 4]);
}

#define BUF 2097152
__device__ float SCR[8*BUF + 2*BB*NN + 256 + 5*128 + 1024];

__device__ __forceinline__ void bn_coef(const float* __restrict__ stat, const float* __restrict__ g,
                                        const float* __restrict__ be, int c, float& sc, float& sh) {
    const float inv = 1.0f / (float)NBTOT;
    float mean = stat[c] * inv;
    float var = stat[64 + c] * inv - mean * mean;
    float r = rsqrtf(var + 1e-5f);
    sc = g[c] * r; sh = be[c] - sc * mean;
}

__global__ void k_stats1(const float* __restrict__ d, int C, float* __restrict__ st2) {
    int c = blockIdx.x, b = blockIdx.y;
    const float* p = d + (b * C + c) * NN;
    float s = 0.f, sq = 0.f;
    for (int i = threadIdx.x; i < NN; i += 256) { float v = p[i]; s += v; sq += v * v; }
    __shared__ float shs[8], shq[8];
    for (int o = 16; o; o >>= 1) { s += __shfl_down_sync(~0u, s, o); sq += __shfl_down_sync(~0u, sq, o); }
    if ((threadIdx.x & 31) == 0) { shs[threadIdx.x >> 5] = s; shq[threadIdx.x >> 5] = sq; }
    __syncthreads();
    if (threadIdx.x == 0) {
        float S = 0.f, Q = 0.f;
        #pragma unroll
        for (int i = 0; i < 8; i++) { S += shs[i]; Q += shq[i]; }
        st2[b * 128 + c] = S; st2[b * 128 + 64 + c] = Q;
    }
}
__global__ void k_stats2(const float* __restrict__ st2, int C, float* __restrict__ stat) {
    int t = threadIdx.x;
    if (t < C) {
        float S = 0.f, Q = 0.f;
        #pragma unroll
        for (int b = 0; b < BB; b++) { S += st2[b * 128 + t]; Q += st2[b * 128 + 64 + t]; }
        stat[t] = S; stat[64 + t] = Q;
    }
}

__global__ void k_conv1(const float* __restrict__ x, const float* __restrict__ w,
                        const float* __restrict__ bias, float* __restrict__ y) {
    __shared__ float ws[192], bs[32];
    int t = threadIdx.x;
    if (t < 192) ws[t] = w[t];
    if (t < 32) bs[t] = bias[t];
    __syncthreads();
    int b = blockIdx.y, n = blockIdx.x * 256 + t;
    float in[6];
    #pragma unroll
    for (int c = 0; c < 6; c++) in[c] = x[(b * 6 + c) * NN + n];
    #pragma unroll
    for (int o = 0; o < 32; o++) {
        float a = bs[o];
        #pragma unroll
        for (int c = 0; c < 6; c++) a = fmaf(ws[o * 6 + c], in[c], a);
        y[(b * 32 + o) * NN + n] = a;
    }
}

__global__ void k_bnconv32(const float* __restrict__ yin, const float* __restrict__ stat,
                           const float* __restrict__ g, const float* __restrict__ be,
                           const float* __restrict__ w, const float* __restrict__ bias,
                           float* __restrict__ yout) {
    __shared__ float ws[1024], bs[32], sc[32], sh[32];
    int t = threadIdx.x;
    for (int i = t; i < 1024; i += 256) ws[i] = w[i];
    if (t < 32) { bs[t] = bias[t]; bn_coef(stat, g, be, t, sc[t], sh[t]); }
    __syncthreads();
    int b = blockIdx.y, n = blockIdx.x * 256 + t;
    float in[32];
    #pragma unroll
    for (int c = 0; c < 32; c++) in[c] = fmaxf(fmaf(sc[c], yin[(b * 32 + c) * NN + n], sh[c]), 0.f);
    for (int o = 0; o < 32; o++) {
        float a = bs[o];
        #pragma unroll
        for (int c = 0; c < 32; c++) a = fmaf(ws[o * 32 + c], in[c], a);
        yout[(b * 32 + o) * NN + n] = a;
    }
}

// BN+relu -> h (C-major); qkT n-major; v C-major
template<int C>
__global__ void k_bnqkv(const float* __restrict__ yin, const float* __restrict__ stat,
                        const float* __restrict__ g, const float* __restrict__ be,
                        const float* __restrict__ wqk, const float* __restrict__ wv,
                        const float* __restrict__ bv,
                        float* __restrict__ h, float* __restrict__ qkT, float* __restrict__ v) {
    __shared__ float wq_s[C*C], wv_s[C*C], bvs[C], sc[C], sh[C];
    int t = threadIdx.x;
    for (int i = t; i < C*C; i += 256) { wq_s[i] = wqk[i]; wv_s[i] = wv[i]; }
    if (t < C) { bvs[t] = bv[t]; bn_coef(stat, g, be, t, sc[t], sh[t]); }
    __syncthreads();
    int b = blockIdx.y, n = blockIdx.x * 256 + t;
    float in[C];
    #pragma unroll
    for (int c = 0; c < C; c++) {
        float val = fmaxf(fmaf(sc[c], yin[(b * C + c) * NN + n], sh[c]), 0.f);
        in[c] = val;
        h[(b * C + c) * NN + n] = val;
    }
    float* qd = qkT + ((size_t)b * NN + n) * C;
    for (int og = 0; og < C; og += 4) {
        float qv[4];
        #pragma unroll
        for (int oo = 0; oo < 4; oo++) {
            int o = og + oo;
            float aq = 0.f, av = bvs[o];
            #pragma unroll
            for (int c = 0; c < C; c++) { aq = fmaf(wq_s[o * C + c], in[c], aq); av = fmaf(wv_s[o * C + c], in[c], av); }
            qv[oo] = aq;
            v[(b * C + o) * NN + n] = av;
        }
        *(float4*)(qd + og) = make_float4(qv[0], qv[1], qv[2], qv[3]);
    }
}

// load [ROWS x C] n-major tile -> padded hi/lo smem (stride C+4)
template<int C, int ROWS>
__device__ __forceinline__ void ldsplit(const float* __restrict__ src, float* hi, float* lo, int t) {
    constexpr int S = C + 4;
    for (int qq = t; qq < ROWS * C / 4; qq += 256) {
        int row = qq / (C / 4), c = (qq % (C / 4)) * 4;
        float4 v4 = *(const float4*)(src + row * C + c);
        float h0 = tf32r(v4.x), h1 = tf32r(v4.y), h2 = tf32r(v4.z), h3 = tf32r(v4.w);
        *(float4*)(hi + row * S + c) = make_float4(h0, h1, h2, h3);
        *(float4*)(lo + row * S + c) = make_float4(v4.x - h0, v4.y - h1, v4.z - h2, v4.w - h3);
    }
}

// ---- pass A: S = Qn x Qm^T via mma.sync tf32; per-row online (M, L) ----
template<int C>
__global__ void __launch_bounds__(256) k_gramA(const float* __restrict__ qkT,
                                               float* __restrict__ Mr, float* __restrict__ iLv) {
    constexpr int S = C + 4;
    extern __shared__ float sm[];
    float *Ah = sm, *Al = Ah + 128*S, *Bh = Al + 128*S, *Bl = Bh + 128*S;
    float *RM = Bl + 128*S, *RL = RM + 256;
    const int t = threadIdx.x, w = t >> 5, lane = t & 31;
    const int b = blockIdx.y, n0 = blockIdx.x * 128;
    const int rw = (w >> 1) * 32, cw = (w & 1) * 64;
    const int r = lane >> 2, q = lane & 3;
    ldsplit<C, 128>(qkT + ((size_t)(b * NN + n0)) * C, Ah, Al, t);
    float Mv[4], Lv[4];
    #pragma unroll
    for (int i = 0; i < 4; i++) { Mv[i] = -1e30f; Lv[i] = 0.f; }
    for (int mt = 0; mt < 32; mt++) {
        __syncthreads();
        ldsplit<C, 128>(qkT + ((size_t)(b * NN + mt * 128)) * C, Bh, Bl, t);
        __syncthreads();
        float acc[2][8][4];
        #pragma unroll
        for (int rf = 0; rf < 2; rf++)
            #pragma unroll
            for (int j = 0; j < 8; j++)
                #pragma unroll
                for (int e = 0; e < 4; e++) acc[rf][j][e] = 0.f;
        #pragma unroll
        for (int ks = 0; ks < C / 8; ks++) {
            int kb = ks * 8;
            uint32_t ah[2][4], al[2][4];
            #pragma unroll
            for (int rf = 0; rf < 2; rf++) {
                ldfragA(ah[rf], Ah, S, rw + rf * 16, kb, r, q);
                ldfragA(al[rf], Al, S, rw + rf * 16, kb, r, q);
            }
            #pragma unroll
            for (int j = 0; j < 8; j++) {
                int cb = cw + j * 8;
                uint32_t bh0 = __float_as_uint(Bh[(cb + r) * S + kb + q]);
                uint32_t bh1 = __float_as_uint(Bh[(cb + r) * S + kb + q + 4]);
                uint32_t bl0 = __float_as_uint(Bl[(cb + r) * S + kb + q]);
                uint32_t bl1 = __float_as_uint(Bl[(cb + r) * S + kb + q + 4]);
                #pragma unroll
                for (int rf = 0; rf < 2; rf++) {
                    mma8(acc[rf][j], ah[rf], bh0, bh1);
                    mma8(acc[rf][j], ah[rf], bl0, bl1);
                    mma8(acc[rf][j], al[rf], bh0, bh1);
                }
            }
        }
        #pragma unroll
        for (int rf = 0; rf < 2; rf++)
            #pragma unroll
            for (int h = 0; h < 2; h++) {
                int i = rf * 2 + h;
                float tm = -1e30f;
                #pragma unroll
                for (int j = 0; j < 8; j++) tm = fmaxf(tm, fmaxf(acc[rf][j][2*h], acc[rf][j][2*h+1]));
                float Mn = fmaxf(Mv[i], tm);
                float l = Lv[i] * __expf(Mv[i] - Mn);
                #pragma unroll
                for (int j = 0; j < 8; j++)
                    l += __expf(acc[rf][j][2*h] - Mn) + __expf(acc[rf][j][2*h+1] - Mn);
                Mv[i] = Mn; Lv[i] = l;
            }
    }
    #pragma unroll
    for (int i = 0; i < 4; i++)
        #pragma unroll
        for (int o = 1; o <= 2; o <<= 1) {
            float M2 = __shfl_xor_sync(~0u, Mv[i], o);
            float L2 = __shfl_xor_sync(~0u, Lv[i], o);
            float Mn = fmaxf(Mv[i], M2);
            Lv[i] = Lv[i] * __expf(Mv[i] - Mn) + L2 * __expf(M2 - Mn);
            Mv[i] = Mn;
        }
    __syncthreads();
    if (q == 0) {
        #pragma unroll
        for (int i = 0; i < 4; i++) {
            int row = rw + (i >> 1) * 16 + (i & 1) * 8 + r;
            RM[row * 2 + (w & 1)] = Mv[i];
            RL[row * 2 + (w & 1)] = Lv[i];
        }
    }
    __syncthreads();
    if (t < 128) {
        float M0 = RM[t*2], M1 = RM[t*2+1], L0 = RL[t*2], L1 = RL[t*2+1];
        float Mn = fmaxf(M0, M1);
        float L = L0 * __expf(M0 - Mn) + L1 * __expf(M1 - Mn);
        Mr[b * NN + n0 + t] = Mn;
        iLv[b * NN + n0 + t] = 1.0f / L;
    }
}

// ---- pass B: S' recompute + exp + col sums + xr^T = E x V' (acc in regs) ----
template<int C>
__global__ void __launch_bounds__(256) k_gramB(const float* __restrict__ qkT,
                                               const float* __restrict__ v,
                                               const float* __restrict__ Mr,
                                               const float* __restrict__ iLv,
                                               float* __restrict__ xrT) {
    constexpr int S = C + 4, SE = 68, NJ2 = C / 16;
    extern __shared__ float sm[];
    float *Qmh = sm, *Qml = Qmh + 128*S, *Qnh = Qml + 128*S, *Qnl = Qnh + 64*S;
    float *Vh = Qnl + 64*S, *Vl = Vh + C*SE, *Eh = Vl + C*SE, *El = Eh + 128*SE;
    float *Msh = El + 128*SE, *Lsh = Msh + 64, *Red = Lsh + 64, *Sinv = Red + 256;
    const int t = threadIdx.x, w = t >> 5, lane = t & 31;
    const int b = blockIdx.y, m0 = blockIdx.x * 128;
    const int rw = (w >> 1) * 32, cw = (w & 1) * 32, cw2 = (w & 1) * (C / 2);
    const int r = lane >> 2, q = lane & 3;
    ldsplit<C, 128>(qkT + ((size_t)(b * NN + m0)) * C, Qmh, Qml, t);
    float acc2[2][NJ2][4];
    #pragma unroll
    for (int rf = 0; rf < 2; rf++)
        #pragma unroll
        for (int j = 0; j < NJ2; j++)
            #pragma unroll
            for (int e = 0; e < 4; e++) acc2[rf][j][e] = 0.f;
    float sacc[4] = {0.f, 0.f, 0.f, 0.f};
    for (int nt = 0; nt < 64; nt++) {
        const int n0 = nt * 64;
        __syncthreads();
        ldsplit<C, 64>(qkT + ((size_t)(b * NN + n0)) * C, Qnh, Qnl, t);
        for (int qq = t; qq < C * 16; qq += 256) {
            int row = qq >> 4, c4 = (qq & 15) * 4;
            float4 v4 = *(const float4*)(v + ((size_t)(b * C + row)) * NN + n0 + c4);
            float h0 = tf32r(v4.x), h1 = tf32r(v4.y), h2 = tf32r(v4.z), h3 = tf32r(v4.w);
            *(float4*)(Vh + row * SE + c4) = make_float4(h0, h1, h2, h3);
            *(float4*)(Vl + row * SE + c4) = make_float4(v4.x - h0, v4.y - h1, v4.z - h2, v4.w - h3);
        }
        if (t < 64) { Msh[t] = Mr[b * NN + n0 + t]; Lsh[t] = iLv[b * NN + n0 + t]; }
        __syncthreads();
        float accS[2][4][4];
        #pragma unroll
        for (int rf = 0; rf < 2; rf++)
            #pragma unroll
            for (int j = 0; j < 4; j++)
                #pragma unroll
                for (int e = 0; e < 4; e++) accS[rf][j][e] = 0.f;
        #pragma unroll
        for (int ks = 0; ks < C / 8; ks++) {
            int kb = ks * 8;
            uint32_t ah[2][4], al[2][4];
            #pragma unroll
            for (int rf = 0; rf < 2; rf++) {
                ldfragA(ah[rf], Qmh, S, rw + rf * 16, kb, r, q);
                ldfragA(al[rf], Qml, S, rw + rf * 16, kb, r, q);
            }
            #pragma unroll
            for (int j = 0; j < 4; j++) {
                int cb = cw + j * 8;
                uint32_t bh0 = __float_as_uint(Qnh[(cb + r) * S + kb + q]);
                uint32_t bh1 = __float_as_uint(Qnh[(cb + r) * S + kb + q + 4]);
                uint32_t bl0 = __float_as_uint(Qnl[(cb + r) * S + kb + q]);
                uint32_t bl1 = __float_as_uint(Qnl[(cb + r) * S + kb + q + 4]);
                #pragma unroll
                for (int rf = 0; rf < 2; rf++) {
                    mma8(accS[rf][j], ah[rf], bh0, bh1);
                    mma8(accS[rf][j], ah[rf], bl0, bl1);
                    mma8(accS[rf][j], al[rf], bh0, bh1);
                }
            }
        }
        #pragma unroll
        for (int rf = 0; rf < 2; rf++)
            #pragma unroll
            for (int h = 0; h < 2; h++) {
                int row = rw + rf * 16 + h * 8 + r;
                #pragma unroll
                for (int j = 0; j < 4; j++) {
                    int col = cw + j * 8 + 2 * q;
                    float e0 = __expf(accS[rf][j][2*h]   - Msh[col])     * Lsh[col];
                    float e1 = __expf(accS[rf][j][2*h+1] - Msh[col + 1]) * Lsh[col + 1];
                    sacc[rf * 2 + h] += e0 + e1;
                    float h0 = tf32r(e0), h1 = tf32r(e1);
                    *(float2*)(Eh + row * SE + col) = make_float2(h0, h1);
                    *(float2*)(El + row * SE + col) = make_float2(e0 - h0, e1 - h1);
                }
            }
        __syncthreads();
        #pragma unroll
        for (int ks = 0; ks < 8; ks++) {
            int kb = ks * 8;
            uint32_t ah[2][4], al[2][4];
            #pragma unroll
            for (int rf = 0; rf < 2; rf++) {
                ldfragA(ah[rf], Eh, SE, rw + rf * 16, kb, r, q);
                ldfragA(al[rf], El, SE, rw + rf * 16, kb, r, q);
            }
            #pragma unroll
            for (int j = 0; j < NJ2; j++) {
                int cc = cw2 + j * 8;
                uint32_t bh0 = __float_as_uint(Vh[(cc + r) * SE + kb + q]);
                uint32_t bh1 = __float_as_uint(Vh[(cc + r) * SE + kb + q + 4]);
                uint32_t bl0 = __float_as_uint(Vl[(cc + r) * SE + kb + q]);
                uint32_t bl1 = __float_as_uint(Vl[(cc + r) * SE + kb + q + 4]);
                #pragma unroll
                for (int rf = 0; rf < 2; rf++) {
                    mma8(acc2[rf][j], ah[rf], bh0, bh1);
                    mma8(acc2[rf][j], ah[rf], bl0, bl1);
                    mma8(acc2[rf][j], al[rf], bh0, bh1);
                }
            }
        }
    }
    #pragma unroll
    for (int i = 0; i < 4; i++) {
        sacc[i] += __shfl_xor_sync(~0u, sacc[i], 1);
        sacc[i] += __shfl_xor_sync(~0u, sacc[i], 2);
    }
    __syncthreads();
    if (q == 0) {
        #pragma unroll
        for (int i = 0; i < 4; i++) {
            int row = rw + (i >> 1) * 16 + (i & 1) * 8 + r;
            Red[row * 2 + (w & 1)] = sacc[i];
        }
    }
    __syncthreads();
    if (t < 128) Sinv[t] = 1.0f / (1e-9f + Red[t*2] + Red[t*2+1]);
    __syncthreads();
    #pragma unroll
    for (int rf = 0; rf < 2; rf++)
        #pragma unroll
        for (int h = 0; h < 2; h++) {
            int row = rw + rf * 16 + h * 8 + r;
            float si = Sinv[row];
            float* dst = xrT + ((size_t)(b * NN + m0 + row)) * C;
            #pragma unroll
            for (int j = 0; j < NJ2; j++) {
                int col = cw2 + j * 8 + 2 * q;
                *(float2*)(dst + col) = make_float2(acc2[rf][j][2*h] * si, acc2[rf][j][2*h+1] * si);
            }
        }
}

// tp = wt @ (h - xr) + bt  (xrT n-major)
template<int C>
__global__ void k_diffconv(const float* __restrict__ h, const float* __restrict__ xrT,
                           const float* __restrict__ wt, const float* __restrict__ bt,
                           float* __restrict__ tp) {
    __shared__ float ws[C*C], bs[C];
    int t = threadIdx.x;
    for (int i = t; i < C*C; i += 256) ws[i] = wt[i];
    if (t < C) bs[t] = bt[t];
    __syncthreads();
    int b = blockIdx.y, n = blockIdx.x * 256 + t;
    const float* xs = xrT + ((size_t)b * NN + n) * C;
    float din[C];
    #pragma unroll
    for (int c = 0; c < C; c += 4) {
        float4 xv = *(const float4*)(xs + c);
        din[c]     = h[(b * C + c) * NN + n]     - xv.x;
        din[c + 1] = h[(b * C + c + 1) * NN + n] - xv.y;
        din[c + 2] = h[(b * C + c + 2) * NN + n] - xv.z;
        din[c + 3] = h[(b * C + c + 3) * NN + n] - xv.w;
    }
    for (int o = 0; o < C; o++) {
        float a = bs[o];
        #pragma unroll
        for (int c = 0; c < C; c++) a = fmaf(ws[o * C + c], din[c], a);
        tp[(b * C + o) * NN + n] = a;
    }
}

template<int C>
__global__ void k_resid(const float* __restrict__ h, const float* __restrict__ tp,
                        const float* __restrict__ stat, const float* __restrict__ g,
                        const float* __restrict__ be, float* __restrict__ out) {
    int idx = blockIdx.x * 256 + threadIdx.x;
    int c = (idx >> 12) & (C - 1);
    float sc, sh;
    bn_coef(stat, g, be, c, sc, sh);
    out[idx] = h[idx] + fmaxf(fmaf(sc, tp[idx], sh), 0.f);
}

__global__ void k_max(const float* __restrict__ d, float* __restrict__ gf) {
    int bc = blockIdx.x;
    const float* p = d + bc * NN;
    float m = -1e30f;
    for (int i = threadIdx.x; i < NN; i += 256) m = fmaxf(m, p[i]);
    __shared__ float sm_[8];
    for (int o = 16; o; o >>= 1) m = fmaxf(m, __shfl_down_sync(~0u, m, o));
    if ((threadIdx.x & 31) == 0) sm_[threadIdx.x >> 5] = m;
    __syncthreads();
    if (threadIdx.x == 0) {
        float M = sm_[0];
        #pragma unroll
        for (int i = 1; i < 8; i++) M = fmaxf(M, sm_[i]);
        gf[bc] = M;
    }
}

__global__ void k_concatconv(const float* __restrict__ h3, const float* __restrict__ gf1,
                             const float* __restrict__ w3, const float* __restrict__ b3,
                             float* __restrict__ y3) {
    __shared__ float ws[4096], K[64];
    int t = threadIdx.x, b = blockIdx.y;
    for (int i = t; i < 4096; i += 256) ws[i] = w3[i];
    __syncthreads();
    if (t < 64) {
        float a = b3[t];
        #pragma unroll
        for (int c = 0; c < 32; c++) a = fmaf(ws[t * 64 + 32 + c], gf1[b * 32 + c], a);
        K[t] = a;
    }
    __syncthreads();
    int n = blockIdx.x * 256 + t;
    float in[32];
    #pragma unroll
    for (int c = 0; c < 32; c++) in[c] = h3[(b * 32 + c) * NN + n];
    for (int o = 0; o < 64; o++) {
        float a = K[o];
        #pragma unroll
        for (int c = 0; c < 32; c++) a = fmaf(ws[o * 64 + c], in[c], a);
        y3[(b * 64 + o) * NN + n] = a;
    }
}

extern "C" void kernel_launch(void* const* d_in, const int* in_sizes, int n_in,
                              void* d_out, int out_size) {
    const float *x = (const float*)d_in[0], *w1 = (const float*)d_in[1], *b1 = (const float*)d_in[2],
        *g1 = (const float*)d_in[3], *be1 = (const float*)d_in[4], *w2 = (const float*)d_in[5],
        *b2 = (const float*)d_in[6], *g2 = (const float*)d_in[7], *be2 = (const float*)d_in[8],
        *a1_wqk = (const float*)d_in[9], *a1_wv = (const float*)d_in[10], *a1_bv = (const float*)d_in[11],
        *a1_wt = (const float*)d_in[12], *a1_bt = (const float*)d_in[13], *a1_g = (const float*)d_in[14],
        *a1_b = (const float*)d_in[15], *w3 = (const float*)d_in[16], *b3 = (const float*)d_in[17],
        *g3 = (const float*)d_in[18], *be3 = (const float*)d_in[19], *a2_wqk = (const float*)d_in[20],
        *a2_wv = (const float*)d_in[21], *a2_bv = (const float*)d_in[22], *a2_wt = (const float*)d_in[23],
        *a2_bt = (const float*)d_in[24], *a2_g = (const float*)d_in[25], *a2_b = (const float*)d_in[26];

    float* S = nullptr;
    cudaGetSymbolAddress((void**)&S, SCR);
    float *y1 = S, *y2 = S + BUF, *h2 = S + 2*BUF, *qkT = S + 3*BUF, *vb = S + 4*BUF,
          *xrT = S + 5*BUF, *tpb = S + 6*BUF, *h3 = S + 7*BUF;
    float *Mr = S + 8*BUF, *iL = Mr + BB*NN, *gf1 = iL + BB*NN, *st = gf1 + 256, *st2 = st + 5*128;
    float* outh = (float*)d_out;
    float* outgf = outh + BB * 64 * NN;

    int smA32 = (4*128*36 + 512) * 4;
    int smA64 = (4*128*68 + 512) * 4;
    int smB32 = (2*128*36 + 2*64*36 + 2*32*68 + 2*128*68 + 512) * 4;
    int smB64 = (2*128*68 + 2*64*68 + 2*64*68 + 2*128*68 + 512) * 4;
    cudaFuncSetAttribute(k_gramA<32>, cudaFuncAttributeMaxDynamicSharedMemorySize, smA32);
    cudaFuncSetAttribute(k_gramA<64>, cudaFuncAttributeMaxDynamicSharedMemorySize, smA64);
    cudaFuncSetAttribute(k_gramB<32>, cudaFuncAttributeMaxDynamicSharedMemorySize, smB32);
    cudaFuncSetAttribute(k_gramB<64>, cudaFuncAttributeMaxDynamicSharedMemorySize, smB64);

    dim3 gN(NN / 256, BB), gA(32, BB);
    k_conv1<<<gN, 256>>>(x, w1, b1, y1);
    k_stats1<<<dim3(32, BB), 256>>>(y1, 32, st2);
    k_stats2<<<1, 64>>>(st2, 32, st);
    k_bnconv32<<<gN, 256>>>(y1, st, g1, be1, w2, b2, y2);
    k_stats1<<<dim3(32, BB), 256>>>(y2, 32, st2);
    k_stats2<<<1, 64>>>(st2, 32, st + 128);
    k_bnqkv<32><<<gN, 256>>>(y2, st + 128, g2, be2, a1_wqk, a1_wv, a1_bv, h2, qkT, vb);
    k_gramA<32><<<gA, 256, smA32>>>(qkT, Mr, iL);
    k_gramB<32><<<gA, 256, smB32>>>(qkT, vb, Mr, iL, xrT);
    k_diffconv<32><<<gN, 256>>>(h2, xrT, a1_wt, a1_bt, tpb);
    k_stats1<<<dim3(32, BB), 256>>>(tpb, 32, st2);
    k_stats2<<<1, 64>>>(st2, 32, st + 256);
    k_resid<32><<<BB*32*NN/256, 256>>>(h2, tpb, st + 256, a1_g, a1_b, h3);
    k_max<<<BB * 32, 256>>>(h3, gf1);
    k_concatconv<<<gN, 256>>>(h3, gf1, w3, b3, y2);
    k_stats1<<<dim3(64, BB), 256>>>(y2, 64, st2);
    k_stats2<<<1, 64>>>(st2, 64, st + 384);
    k_bnqkv<64><<<gN, 256>>>(y2, st + 384, g3, be3, a2_wqk, a2_wv, a2_bv, y1, qkT, vb);
    k_gramA<64><<<gA, 256, smA64>>>(qkT, Mr, iL);
    k_gramB<64><<<gA, 256, smB64>>>(qkT, vb, Mr, iL, xrT);
    k_diffconv<64><<<gN, 256>>>(y1, xrT, a2_wt, a2_bt, tpb);
    k_stats1<<<dim3(64, BB), 256>>>(tpb, 64, st2);
    k_stats2<<<1, 64>>>(st2, 64, st + 512);
    k_resid<64><<<BB*64*NN/256, 256>>>(y1, tpb, st + 512, a2_g, a2_b, outh);
    k_max<<<BB * 64, 256>>>(outh, outgf);
}

// round 9
// speedup vs baseline: 1.5325x; 1.4479x over previous
#include <cuda_runtime.h>
#include <cuda_fp16.h>
#include <cstdint>

#define NN 4096
#define BB 8
#define NBTOT (BB*NN)
#define LSC 2048.0f
#define ILSC (1.0f/2048.0f)
typedef __half hf;

__device__ __forceinline__ uint32_t pk2(float a, float b) {
    __half2 h = __floats2half2_rn(a, b);
    return *(uint32_t*)&h;
}
__device__ __forceinline__ void mma16(float* d, const uint32_t* a, uint32_t b0, uint32_t b1) {
    asm volatile("mma.sync.aligned.m16n8k16.row.col.f32.f16.f16.f32 "
        "{%0,%1,%2,%3}, {%4,%5,%6,%7}, {%8,%9}, {%0,%1,%2,%3};"
        : "+f"(d[0]), "+f"(d[1]), "+f"(d[2]), "+f"(d[3])
        : "r"(a[0]), "r"(a[1]), "r"(a[2]), "r"(a[3]), "r"(b0), "r"(b1));
}
__device__ __forceinline__ void ldfA(uint32_t* f, const hf* base, int S, int rb, int kb, int r, int q2) {
    f[0] = *(const uint32_t*)(base + (rb + r) * S + kb + q2);
    f[1] = *(const uint32_t*)(base + (rb + r + 8) * S + kb + q2);
    f[2] = *(const uint32_t*)(base + (rb + r) * S + kb + q2 + 8);
    f[3] = *(const uint32_t*)(base + (rb + r + 8) * S + kb + q2 + 8);
}

#define BUF 2097152
__device__ float SCR[8*BUF + 2*BB*NN + 256 + 5*128 + 1024];

__device__ __forceinline__ void bn_coef(const float* __restrict__ stat, const float* __restrict__ g,
                                        const float* __restrict__ be, int c, float& sc, float& sh) {
    const float inv = 1.0f / (float)NBTOT;
    float mean = stat[c] * inv;
    float var = stat[64 + c] * inv - mean * mean;
    float r = rsqrtf(var + 1e-5f);
    sc = g[c] * r; sh = be[c] - sc * mean;
}

__global__ void k_stats1(const float* __restrict__ d, int C, float* __restrict__ st2) {
    int c = blockIdx.x, b = blockIdx.y;
    const float* p = d + (b * C + c) * NN;
    float s = 0.f, sq = 0.f;
    for (int i = threadIdx.x; i < NN; i += 256) { float v = p[i]; s += v; sq += v * v; }
    __shared__ float shs[8], shq[8];
    for (int o = 16; o; o >>= 1) { s += __shfl_down_sync(~0u, s, o); sq += __shfl_down_sync(~0u, sq, o); }
    if ((threadIdx.x & 31) == 0) { shs[threadIdx.x >> 5] = s; shq[threadIdx.x >> 5] = sq; }
    __syncthreads();
    if (threadIdx.x == 0) {
        float S = 0.f, Q = 0.f;
        #pragma unroll
        for (int i = 0; i < 8; i++) { S += shs[i]; Q += shq[i]; }
        st2[b * 128 + c] = S; st2[b * 128 + 64 + c] = Q;
    }
}
__global__ void k_stats2(const float* __restrict__ st2, int C, float* __restrict__ stat) {
    int t = threadIdx.x;
    if (t < C) {
        float S = 0.f, Q = 0.f;
        #pragma unroll
        for (int b = 0; b < BB; b++) { S += st2[b * 128 + t]; Q += st2[b * 128 + 64 + t]; }
        stat[t] = S; stat[64 + t] = Q;
    }
}

__global__ void k_conv1(const float* __restrict__ x, const float* __restrict__ w,
                        const float* __restrict__ bias, float* __restrict__ y) {
    __shared__ float ws[192], bs[32];
    int t = threadIdx.x;
    if (t < 192) ws[t] = w[t];
    if (t < 32) bs[t] = bias[t];
    __syncthreads();
    int b = blockIdx.y, n = blockIdx.x * 256 + t;
    float in[6];
    #pragma unroll
    for (int c = 0; c < 6; c++) in[c] = x[(b * 6 + c) * NN + n];
    #pragma unroll
    for (int o = 0; o < 32; o++) {
        float a = bs[o];
        #pragma unroll
        for (int c = 0; c < 6; c++) a = fmaf(ws[o * 6 + c], in[c], a);
        y[(b * 32 + o) * NN + n] = a;
    }
}

__global__ void k_bnconv32(const float* __restrict__ yin, const float* __restrict__ stat,
                           const float* __restrict__ g, const float* __restrict__ be,
                           const float* __restrict__ w, const float* __restrict__ bias,
                           float* __restrict__ yout) {
    __shared__ float ws[1024], bs[32], sc[32], sh[32];
    int t = threadIdx.x;
    for (int i = t; i < 1024; i += 256) ws[i] = w[i];
    if (t < 32) { bs[t] = bias[t]; bn_coef(stat, g, be, t, sc[t], sh[t]); }
    __syncthreads();
    int b = blockIdx.y, n = blockIdx.x * 256 + t;
    float in[32];
    #pragma unroll
    for (int c = 0; c < 32; c++) in[c] = fmaxf(fmaf(sc[c], yin[(b * 32 + c) * NN + n], sh[c]), 0.f);
    for (int o = 0; o < 32; o++) {
        float a = bs[o];
        #pragma unroll
        for (int c = 0; c < 32; c++) a = fmaf(ws[o * 32 + c], in[c], a);
        yout[(b * 32 + o) * NN + n] = a;
    }
}

template<int C>
__global__ void k_bnqkv(const float* __restrict__ yin, const float* __restrict__ stat,
                        const float* __restrict__ g, const float* __restrict__ be,
                        const float* __restrict__ wqk, const float* __restrict__ wv,
                        const float* __restrict__ bv,
                        float* __restrict__ h, float* __restrict__ qkT, float* __restrict__ v) {
    __shared__ float wq_s[C*C], wv_s[C*C], bvs[C], sc[C], sh[C];
    int t = threadIdx.x;
    for (int i = t; i < C*C; i += 256) { wq_s[i] = wqk[i]; wv_s[i] = wv[i]; }
    if (t < C) { bvs[t] = bv[t]; bn_coef(stat, g, be, t, sc[t], sh[t]); }
    __syncthreads();
    int b = blockIdx.y, n = blockIdx.x * 256 + t;
    float in[C];
    #pragma unroll
    for (int c = 0; c < C; c++) {
        float val = fmaxf(fmaf(sc[c], yin[(b * C + c) * NN + n], sh[c]), 0.f);
        in[c] = val;
        h[(b * C + c) * NN + n] = val;
    }
    float* qd = qkT + ((size_t)b * NN + n) * C;
    for (int og = 0; og < C; og += 4) {
        float qv[4];
        #pragma unroll
        for (int oo = 0; oo < 4; oo++) {
            int o = og + oo;
            float aq = 0.f, av = bvs[o];
            #pragma unroll
            for (int c = 0; c < C; c++) { aq = fmaf(wq_s[o * C + c], in[c], aq); av = fmaf(wv_s[o * C + c], in[c], av); }
            qv[oo] = aq;
            v[(b * C + o) * NN + n] = av;
        }
        *(float4*)(qd + og) = make_float4(qv[0], qv[1], qv[2], qv[3]);
    }
}

// load [ROWS x C] n-major floats -> fp16 hi + scaled-lo smem (stride C+8 halves)
template<int C, int ROWS>
__device__ __forceinline__ void ldsplit(const float* __restrict__ src, hf* hi, hf* lo, int t) {
    constexpr int S = C + 8;
    for (int qq = t; qq < ROWS * C / 4; qq += 256) {
        int row = qq / (C / 4), c = (qq % (C / 4)) * 4;
        float4 v4 = *(const float4*)(src + row * C + c);
        hf h0 = __float2half_rn(v4.x), h1 = __float2half_rn(v4.y),
           h2 = __float2half_rn(v4.z), h3 = __float2half_rn(v4.w);
        float l0 = (v4.x - __half2float(h0)) * LSC, l1 = (v4.y - __half2float(h1)) * LSC,
              l2 = (v4.z - __half2float(h2)) * LSC, l3 = (v4.w - __half2float(h3)) * LSC;
        uint32_t u0 = ((uint32_t)__half_as_ushort(h1) << 16) | __half_as_ushort(h0);
        uint32_t u1 = ((uint32_t)__half_as_ushort(h3) << 16) | __half_as_ushort(h2);
        *(uint2*)(hi + row * S + c) = make_uint2(u0, u1);
        *(uint2*)(lo + row * S + c) = make_uint2(pk2(l0, l1), pk2(l2, l3));
    }
}

// ---- pass A: S = Qn x Qm^T (fp16 hi + scaled lo, dual acc); per-row online (M, L) ----
template<int C>
__global__ void __launch_bounds__(256) k_gramA(const float* __restrict__ qkT,
                                               float* __restrict__ Mr, float* __restrict__ iLv) {
    constexpr int S = C + 8;
    extern __shared__ float smf[];
    float *RM = smf, *RL = smf + 256;
    hf* Ah = (hf*)(smf + 512);
    hf *Al = Ah + 128*S, *Bh = Al + 128*S, *Bl = Bh + 128*S;
    const int t = threadIdx.x, w = t >> 5, lane = t & 31;
    const int b = blockIdx.y, n0 = blockIdx.x * 128;
    const int rw = (w >> 1) * 32, cw = (w & 1) * 64;
    const int r = lane >> 2, q2 = (lane & 3) * 2;
    ldsplit<C, 128>(qkT + ((size_t)(b * NN + n0)) * C, Ah, Al, t);
    float Mv[4], Lv[4];
    #pragma unroll
    for (int i = 0; i < 4; i++) { Mv[i] = -1e30f; Lv[i] = 0.f; }
    for (int mt = 0; mt < 32; mt++) {
        __syncthreads();
        ldsplit<C, 128>(qkT + ((size_t)(b * NN + mt * 128)) * C, Bh, Bl, t);
        __syncthreads();
        float accH[2][8][4], accX[2][8][4];
        #pragma unroll
        for (int rf = 0; rf < 2; rf++)
            #pragma unroll
            for (int j = 0; j < 8; j++)
                #pragma unroll
                for (int e = 0; e < 4; e++) { accH[rf][j][e] = 0.f; accX[rf][j][e] = 0.f; }
        #pragma unroll
        for (int ks = 0; ks < C / 16; ks++) {
            int kb = ks * 16;
            uint32_t ah[2][4], al[2][4];
            #pragma unroll
            for (int rf = 0; rf < 2; rf++) {
                ldfA(ah[rf], Ah, S, rw + rf * 16, kb, r, q2);
                ldfA(al[rf], Al, S, rw + rf * 16, kb, r, q2);
            }
            #pragma unroll
            for (int j = 0; j < 8; j++) {
                int cb = cw + j * 8;
                uint32_t bh0 = *(const uint32_t*)(Bh + (cb + r) * S + kb + q2);
                uint32_t bh1 = *(const uint32_t*)(Bh + (cb + r) * S + kb + q2 + 8);
                uint32_t bl0 = *(const uint32_t*)(Bl + (cb + r) * S + kb + q2);
                uint32_t bl1 = *(const uint32_t*)(Bl + (cb + r) * S + kb + q2 + 8);
                #pragma unroll
                for (int rf = 0; rf < 2; rf++) {
                    mma16(accH[rf][j], ah[rf], bh0, bh1);
                    mma16(accX[rf][j], ah[rf], bl0, bl1);
                    mma16(accX[rf][j], al[rf], bh0, bh1);
                }
            }
        }
        #pragma unroll
        for (int rf = 0; rf < 2; rf++)
            #pragma unroll
            for (int h = 0; h < 2; h++) {
                int i = rf * 2 + h;
                float sv[16];
                #pragma unroll
                for (int j = 0; j < 8; j++) {
                    sv[2*j]   = fmaf(accX[rf][j][2*h],   ILSC, accH[rf][j][2*h]);
                    sv[2*j+1] = fmaf(accX[rf][j][2*h+1], ILSC, accH[rf][j][2*h+1]);
                }
                float tm = -1e30f;
                #pragma unroll
                for (int j = 0; j < 16; j++) tm = fmaxf(tm, sv[j]);
                float Mn = fmaxf(Mv[i], tm);
                float l = Lv[i] * __expf(Mv[i] - Mn);
                #pragma unroll
                for (int j = 0; j < 16; j++) l += __expf(sv[j] - Mn);
                Mv[i] = Mn; Lv[i] = l;
            }
    }
    #pragma unroll
    for (int i = 0; i < 4; i++)
        #pragma unroll
        for (int o = 1; o <= 2; o <<= 1) {
            float M2 = __shfl_xor_sync(~0u, Mv[i], o);
            float L2 = __shfl_xor_sync(~0u, Lv[i], o);
            float Mn = fmaxf(Mv[i], M2);
            Lv[i] = Lv[i] * __expf(Mv[i] - Mn) + L2 * __expf(M2 - Mn);
            Mv[i] = Mn;
        }
    __syncthreads();
    if ((lane & 3) == 0) {
        #pragma unroll
        for (int i = 0; i < 4; i++) {
            int row = rw + (i >> 1) * 16 + (i & 1) * 8 + r;
            RM[row * 2 + (w & 1)] = Mv[i];
            RL[row * 2 + (w & 1)] = Lv[i];
        }
    }
    __syncthreads();
    if (t < 128) {
        float M0 = RM[t*2], M1 = RM[t*2+1], L0 = RL[t*2], L1 = RL[t*2+1];
        float Mn = fmaxf(M0, M1);
        float L = L0 * __expf(M0 - Mn) + L1 * __expf(M1 - Mn);
        Mr[b * NN + n0 + t] = Mn;
        iLv[b * NN + n0 + t] = 1.0f / L;
    }
}

// ---- pass B: S' recompute + exp (E hi + scaled lo) + col sums + xr^T = E x V (dual acc) ----
template<int C>
__global__ void __launch_bounds__(256) k_gramB(const float* __restrict__ qkT,
                                               const float* __restrict__ v,
                                               const float* __restrict__ Mr,
                                               const float* __restrict__ iLv,
                                               float* __restrict__ xrT) {
    constexpr int S = C + 8, SE = 72, NJ2 = C / 16;
    extern __shared__ float smf[];
    float *Msh = smf, *Lsh = smf + 64, *Red = smf + 128, *Sinv = smf + 384;
    hf* Qmh = (hf*)(smf + 512);
    hf *Qml = Qmh + 128*S, *Qnh = Qml + 128*S, *Qnl = Qnh + 64*S;
    hf *Vh = Qnl + 64*S, *Vl = Vh + C*SE, *Eh = Vl + C*SE, *El = Eh + 128*SE;
    const int t = threadIdx.x, w = t >> 5, lane = t & 31;
    const int b = blockIdx.y, m0 = blockIdx.x * 128;
    const int rw = (w >> 1) * 32, cw = (w & 1) * 32, cw2 = (w & 1) * (C / 2);
    const int r = lane >> 2, q2 = (lane & 3) * 2;
    ldsplit<C, 128>(qkT + ((size_t)(b * NN + m0)) * C, Qmh, Qml, t);
    float acc2H[2][NJ2][4], acc2X[2][NJ2][4];
    #pragma unroll
    for (int rf = 0; rf < 2; rf++)
        #pragma unroll
        for (int j = 0; j < NJ2; j++)
            #pragma unroll
            for (int e = 0; e < 4; e++) { acc2H[rf][j][e] = 0.f; acc2X[rf][j][e] = 0.f; }
    float sacc[4] = {0.f, 0.f, 0.f, 0.f};
    for (int nt = 0; nt < 64; nt++) {
        const int n0 = nt * 64;
        __syncthreads();
        ldsplit<C, 64>(qkT + ((size_t)(b * NN + n0)) * C, Qnh, Qnl, t);
        for (int qq = t; qq < C * 16; qq += 256) {
            int row = qq >> 4, c4 = (qq & 15) * 4;
            float4 v4 = *(const float4*)(v + ((size_t)(b * C + row)) * NN + n0 + c4);
            hf h0 = __float2half_rn(v4.x), h1 = __float2half_rn(v4.y),
               h2 = __float2half_rn(v4.z), h3 = __float2half_rn(v4.w);
            uint32_t u0 = ((uint32_t)__half_as_ushort(h1) << 16) | __half_as_ushort(h0);
            uint32_t u1 = ((uint32_t)__half_as_ushort(h3) << 16) | __half_as_ushort(h2);
            *(uint2*)(Vh + row * SE + c4) = make_uint2(u0, u1);
            *(uint2*)(Vl + row * SE + c4) = make_uint2(
                pk2((v4.x - __half2float(h0)) * LSC, (v4.y - __half2float(h1)) * LSC),
                pk2((v4.z - __half2float(h2)) * LSC, (v4.w - __half2float(h3)) * LSC));
        }
        if (t < 64) { Msh[t] = Mr[b * NN + n0 + t]; Lsh[t] = iLv[b * NN + n0 + t]; }
        __syncthreads();
        float accS[2][4][4], accSX[2][4][4];
        #pragma unroll
        for (int rf = 0; rf < 2; rf++)
            #pragma unroll
            for (int j = 0; j < 4; j++)
                #pragma unroll
                for (int e = 0; e < 4; e++) { accS[rf][j][e] = 0.f; accSX[rf][j][e] = 0.f; }
        #pragma unroll
        for (int ks = 0; ks < C / 16; ks++) {
            int kb = ks * 16;
            uint32_t ah[2][4], al[2][4];
            #pragma unroll
            for (int rf = 0; rf < 2; rf++) {
                ldfA(ah[rf], Qmh, S, rw + rf * 16, kb, r, q2);
                ldfA(al[rf], Qml, S, rw + rf * 16, kb, r, q2);
            }
            #pragma unroll
            for (int j = 0; j < 4; j++) {
                int cb = cw + j * 8;
                uint32_t bh0 = *(const uint32_t*)(Qnh + (cb + r) * S + kb + q2);
                uint32_t bh1 = *(const uint32_t*)(Qnh + (cb + r) * S + kb + q2 + 8);
                uint32_t bl0 = *(const uint32_t*)(Qnl + (cb + r) * S + kb + q2);
                uint32_t bl1 = *(const uint32_t*)(Qnl + (cb + r) * S + kb + q2 + 8);
                #pragma unroll
                for (int rf = 0; rf < 2; rf++) {
                    mma16(accS[rf][j], ah[rf], bh0, bh1);
                    mma16(accSX[rf][j], ah[rf], bl0, bl1);
                    mma16(accSX[rf][j], al[rf], bh0, bh1);
                }
            }
        }
        #pragma unroll
        for (int rf = 0; rf < 2; rf++)
            #pragma unroll
            for (int h = 0; h < 2; h++) {
                int row = rw + rf * 16 + h * 8 + r;
                #pragma unroll
                for (int j = 0; j < 4; j++) {
                    int col = cw + j * 8 + q2;
                    float s0 = fmaf(accSX[rf][j][2*h],   ILSC, accS[rf][j][2*h]);
                    float s1 = fmaf(accSX[rf][j][2*h+1], ILSC, accS[rf][j][2*h+1]);
                    float e0 = __expf(s0 - Msh[col])     * Lsh[col];
                    float e1 = __expf(s1 - Msh[col + 1]) * Lsh[col + 1];
                    sacc[rf * 2 + h] += e0 + e1;
                    hf eh0 = __float2half_rn(e0), eh1 = __float2half_rn(e1);
                    *(uint32_t*)(Eh + row * SE + col) =
                        ((uint32_t)__half_as_ushort(eh1) << 16) | __half_as_ushort(eh0);
                    *(uint32_t*)(El + row * SE + col) =
                        pk2((e0 - __half2float(eh0)) * LSC, (e1 - __half2float(eh1)) * LSC);
                }
            }
        __syncthreads();
        #pragma unroll
        for (int ks = 0; ks < 4; ks++) {
            int kb = ks * 16;
            uint32_t ef[2][4], efl[2][4];
            #pragma unroll
            for (int rf = 0; rf < 2; rf++) {
                ldfA(ef[rf], Eh, SE, rw + rf * 16, kb, r, q2);
                ldfA(efl[rf], El, SE, rw + rf * 16, kb, r, q2);
            }
            #pragma unroll
            for (int j = 0; j < NJ2; j++) {
                int cc = cw2 + j * 8;
                uint32_t bh0 = *(const uint32_t*)(Vh + (cc + r) * SE + kb + q2);
                uint32_t bh1 = *(const uint32_t*)(Vh + (cc + r) * SE + kb + q2 + 8);
                uint32_t bl0 = *(const uint32_t*)(Vl + (cc + r) * SE + kb + q2);
                uint32_t bl1 = *(const uint32_t*)(Vl + (cc + r) * SE + kb + q2 + 8);
                #pragma unroll
                for (int rf = 0; rf < 2; rf++) {
                    mma16(acc2H[rf][j], ef[rf], bh0, bh1);
                    mma16(acc2X[rf][j], ef[rf], bl0, bl1);
                    mma16(acc2X[rf][j], efl[rf], bh0, bh1);
                }
            }
        }
    }
    #pragma unroll
    for (int i = 0; i < 4; i++) {
        sacc[i] += __shfl_xor_sync(~0u, sacc[i], 1);
        sacc[i] += __shfl_xor_sync(~0u, sacc[i], 2);
    }
    __syncthreads();
    if ((lane & 3) == 0) {
        #pragma unroll
        for (int i = 0; i < 4; i++) {
            int row = rw + (i >> 1) * 16 + (i & 1) * 8 + r;
            Red[row * 2 + (w & 1)] = sacc[i];
        }
    }
    __syncthreads();
    if (t < 128) Sinv[t] = 1.0f / (1e-9f + Red[t*2] + Red[t*2+1]);
    __syncthreads();
    #pragma unroll
    for (int rf = 0; rf < 2; rf++)
        #pragma unroll
        for (int h = 0; h < 2; h++) {
            int row = rw + rf * 16 + h * 8 + r;
            float si = Sinv[row];
            float* dst = xrT + ((size_t)(b * NN + m0 + row)) * C;
            #pragma unroll
            for (int j = 0; j < NJ2; j++) {
                int col = cw2 + j * 8 + q2;
                float u0 = fmaf(acc2X[rf][j][2*h],   ILSC, acc2H[rf][j][2*h]);
                float u1 = fmaf(acc2X[rf][j][2*h+1], ILSC, acc2H[rf][j][2*h+1]);
                *(float2*)(dst + col) = make_float2(u0 * si, u1 * si);
            }
        }
}

template<int C>
__global__ void k_diffconv(const float* __restrict__ h, const float* __restrict__ xrT,
                           const float* __restrict__ wt, const float* __restrict__ bt,
                           float* __restrict__ tp) {
    __shared__ float ws[C*C], bs[C];
    int t = threadIdx.x;
    for (int i = t; i < C*C; i += 256) ws[i] = wt[i];
    if (t < C) bs[t] = bt[t];
    __syncthreads();
    int b = blockIdx.y, n = blockIdx.x * 256 + t;
    const float* xs = xrT + ((size_t)b * NN + n) * C;
    float din[C];
    #pragma unroll
    for (int c = 0; c < C; c += 4) {
        float4 xv = *(const float4*)(xs + c);
        din[c]     = h[(b * C + c) * NN + n]     - xv.x;
        din[c + 1] = h[(b * C + c + 1) * NN + n] - xv.y;
        din[c + 2] = h[(b * C + c + 2) * NN + n] - xv.z;
        din[c + 3] = h[(b * C + c + 3) * NN + n] - xv.w;
    }
    for (int o = 0; o < C; o++) {
        float a = bs[o];
        #pragma unroll
        for (int c = 0; c < C; c++) a = fmaf(ws[o * C + c], din[c], a);
        tp[(b * C + o) * NN + n] = a;
    }
}

template<int C>
__global__ void k_resid(const float* __restrict__ h, const float* __restrict__ tp,
                        const float* __restrict__ stat, const float* __restrict__ g,
                        const float* __restrict__ be, float* __restrict__ out) {
    int idx = blockIdx.x * 256 + threadIdx.x;
    int c = (idx >> 12) & (C - 1);
    float sc, sh;
    bn_coef(stat, g, be, c, sc, sh);
    out[idx] = h[idx] + fmaxf(fmaf(sc, tp[idx], sh), 0.f);
}

__global__ void k_max(const float* __restrict__ d, float* __restrict__ gf) {
    int bc = blockIdx.x;
    const float* p = d + bc * NN;
    float m = -1e30f;
    for (int i = threadIdx.x; i < NN; i += 256) m = fmaxf(m, p[i]);
    __shared__ float sm_[8];
    for (int o = 16; o; o >>= 1) m = fmaxf(m, __shfl_down_sync(~0u, m, o));
    if ((threadIdx.x & 31) == 0) sm_[threadIdx.x >> 5] = m;
    __syncthreads();
    if (threadIdx.x == 0) {
        float M = sm_[0];
        #pragma unroll
        for (int i = 1; i < 8; i++) M = fmaxf(M, sm_[i]);
        gf[bc] = M;
    }
}

__global__ void k_concatconv(const float* __restrict__ h3, const float* __restrict__ gf1,
                             const float* __restrict__ w3, const float* __restrict__ b3,
                             float* __restrict__ y3) {
    __shared__ float ws[4096], K[64];
    int t = threadIdx.x, b = blockIdx.y;
    for (int i = t; i < 4096; i += 256) ws[i] = w3[i];
    __syncthreads();
    if (t < 64) {
        float a = b3[t];
        #pragma unroll
        for (int c = 0; c < 32; c++) a = fmaf(ws[t * 64 + 32 + c], gf1[b * 32 + c], a);
        K[t] = a;
    }
    __syncthreads();
    int n = blockIdx.x * 256 + t;
    float in[32];
    #pragma unroll
    for (int c = 0; c < 32; c++) in[c] = h3[(b * 32 + c) * NN + n];
    for (int o = 0; o < 64; o++) {
        float a = K[o];
        #pragma unroll
        for (int c = 0; c < 32; c++) a = fmaf(ws[o * 64 + c], in[c], a);
        y3[(b * 64 + o) * NN + n] = a;
    }
}

extern "C" void kernel_launch(void* const* d_in, const int* in_sizes, int n_in,
                              void* d_out, int out_size) {
    const float *x = (const float*)d_in[0], *w1 = (const float*)d_in[1], *b1 = (const float*)d_in[2],
        *g1 = (const float*)d_in[3], *be1 = (const float*)d_in[4], *w2 = (const float*)d_in[5],
        *b2 = (const float*)d_in[6], *g2 = (const float*)d_in[7], *be2 = (const float*)d_in[8],
        *a1_wqk = (const float*)d_in[9], *a1_wv = (const float*)d_in[10], *a1_bv = (const float*)d_in[11],
        *a1_wt = (const float*)d_in[12], *a1_bt = (const float*)d_in[13], *a1_g = (const float*)d_in[14],
        *a1_b = (const float*)d_in[15], *w3 = (const float*)d_in[16], *b3 = (const float*)d_in[17],
        *g3 = (const float*)d_in[18], *be3 = (const float*)d_in[19], *a2_wqk = (const float*)d_in[20],
        *a2_wv = (const float*)d_in[21], *a2_bv = (const float*)d_in[22], *a2_wt = (const float*)d_in[23],
        *a2_bt = (const float*)d_in[24], *a2_g = (const float*)d_in[25], *a2_b = (const float*)d_in[26];

    float* S = nullptr;
    cudaGetSymbolAddress((void**)&S, SCR);
    float *y1 = S, *y2 = S + BUF, *h2 = S + 2*BUF, *qkT = S + 3*BUF, *vb = S + 4*BUF,
          *xrT = S + 5*BUF, *tpb = S + 6*BUF, *h3 = S + 7*BUF;
    float *Mr = S + 8*BUF, *iL = Mr + BB*NN, *gf1 = iL + BB*NN, *st = gf1 + 256, *st2 = st + 5*128;
    float* outh = (float*)d_out;
    float* outgf = outh + BB * 64 * NN;

    int smA32 = 2048 + 4*128*40*2;
    int smA64 = 2048 + 4*128*72*2;
    int smB32 = 2048 + (2*128*40 + 2*64*40 + 2*32*72 + 2*128*72) * 2;
    int smB64 = 2048 + (2*128*72 + 2*64*72 + 2*64*72 + 2*128*72) * 2;
    cudaFuncSetAttribute(k_gramA<32>, cudaFuncAttributeMaxDynamicSharedMemorySize, smA32);
    cudaFuncSetAttribute(k_gramA<64>, cudaFuncAttributeMaxDynamicSharedMemorySize, smA64);
    cudaFuncSetAttribute(k_gramB<32>, cudaFuncAttributeMaxDynamicSharedMemorySize, smB32);
    cudaFuncSetAttribute(k_gramB<64>, cudaFuncAttributeMaxDynamicSharedMemorySize, smB64);

    dim3 gN(NN / 256, BB), gA(32, BB);
    k_conv1<<<gN, 256>>>(x, w1, b1, y1);
    k_stats1<<<dim3(32, BB), 256>>>(y1, 32, st2);
    k_stats2<<<1, 64>>>(st2, 32, st);
    k_bnconv32<<<gN, 256>>>(y1, st, g1, be1, w2, b2, y2);
    k_stats1<<<dim3(32, BB), 256>>>(y2, 32, st2);
    k_stats2<<<1, 64>>>(st2, 32, st + 128);
    k_bnqkv<32><<<gN, 256>>>(y2, st + 128, g2, be2, a1_wqk, a1_wv, a1_bv, h2, qkT, vb);
    k_gramA<32><<<gA, 256, smA32>>>(qkT, Mr, iL);
    k_gramB<32><<<gA, 256, smB32>>>(qkT, vb, Mr, iL, xrT);
    k_diffconv<32><<<gN, 256>>>(h2, xrT, a1_wt, a1_bt, tpb);
    k_stats1<<<dim3(32, BB), 256>>>(tpb, 32, st2);
    k_stats2<<<1, 64>>>(st2, 32, st + 256);
    k_resid<32><<<BB*32*NN/256, 256>>>(h2, tpb, st + 256, a1_g, a1_b, h3);
    k_max<<<BB * 32, 256>>>(h3, gf1);
    k_concatconv<<<gN, 256>>>(h3, gf1, w3, b3, y2);
    k_stats1<<<dim3(64, BB), 256>>>(y2, 64, st2);
    k_stats2<<<1, 64>>>(st2, 64, st + 384);
    k_bnqkv<64><<<gN, 256>>>(y2, st + 384, g3, be3, a2_wqk, a2_wv, a2_bv, y1, qkT, vb);
    k_gramA<64><<<gA, 256, smA64>>>(qkT, Mr, iL);
    k_gramB<64><<<gA, 256, smB64>>>(qkT, vb, Mr, iL, xrT);
    k_diffconv<64><<<gN, 256>>>(y1, xrT, a2_wt, a2_bt, tpb);
    k_stats1<<<dim3(64, BB), 256>>>(tpb, 64, st2);
    k_stats2<<<1, 64>>>(st2, 64, st + 512);
    k_resid<64><<<BB*64*NN/256, 256>>>(y1, tpb, st + 512, a2_g, a2_b, outh);
    k_max<<<BB * 64, 256>>>(outh, outgf);
}

// round 10
// speedup vs baseline: 2.1851x; 1.4258x over previous
#include <cuda_runtime.h>
#include <cuda_fp16.h>
#include <cstdint>

#define NN 4096
#define BB 8
#define NBTOT (BB*NN)
#define LSC 2048.0f
#define ILSC (1.0f/2048.0f)
typedef __half hf;

__device__ __forceinline__ uint32_t pk2(float a, float b) {
    __half2 h = __floats2half2_rn(a, b);
    return *(uint32_t*)&h;
}
__device__ __forceinline__ void mma16(float* d, const uint32_t* a, uint32_t b0, uint32_t b1) {
    asm volatile("mma.sync.aligned.m16n8k16.row.col.f32.f16.f16.f32 "
        "{%0,%1,%2,%3}, {%4,%5,%6,%7}, {%8,%9}, {%0,%1,%2,%3};"
        : "+f"(d[0]), "+f"(d[1]), "+f"(d[2]), "+f"(d[3])
        : "r"(a[0]), "r"(a[1]), "r"(a[2]), "r"(a[3]), "r"(b0), "r"(b1));
}
__device__ __forceinline__ void ldfA(uint32_t* f, const hf* base, int S, int rb, int kb, int r, int q2) {
    f[0] = *(const uint32_t*)(base + (rb + r) * S + kb + q2);
    f[1] = *(const uint32_t*)(base + (rb + r + 8) * S + kb + q2);
    f[2] = *(const uint32_t*)(base + (rb + r) * S + kb + q2 + 8);
    f[3] = *(const uint32_t*)(base + (rb + r + 8) * S + kb + q2 + 8);
}

#define BUF 2097152
__device__ float SCR[8*BUF + 2*BB*NN + 256 + 5*128 + 1024];

// bn coefficients from 8 per-batch partials (st2[b*128+c]=sum, +64=sumsq)
__device__ __forceinline__ void bn_coef8(const float* __restrict__ st2, const float* __restrict__ g,
                                         const float* __restrict__ be, int c, float& sc, float& sh) {
    float S = 0.f, Q = 0.f;
    #pragma unroll
    for (int b = 0; b < BB; b++) { S += st2[b * 128 + c]; Q += st2[b * 128 + 64 + c]; }
    const float inv = 1.0f / (float)NBTOT;
    float mean = S * inv;
    float var = Q * inv - mean * mean;
    float r = rsqrtf(var + 1e-5f);
    sc = g[c] * r; sh = be[c] - sc * mean;
}

__global__ void k_stats1(const float* __restrict__ d, int C, float* __restrict__ st2) {
    int c = blockIdx.x, b = blockIdx.y;
    const float* p = d + (b * C + c) * NN;
    float s = 0.f, sq = 0.f;
    for (int i = threadIdx.x; i < NN; i += 256) { float v = p[i]; s += v; sq += v * v; }
    __shared__ float shs[8], shq[8];
    for (int o = 16; o; o >>= 1) { s += __shfl_down_sync(~0u, s, o); sq += __shfl_down_sync(~0u, sq, o); }
    if ((threadIdx.x & 31) == 0) { shs[threadIdx.x >> 5] = s; shq[threadIdx.x >> 5] = sq; }
    __syncthreads();
    if (threadIdx.x == 0) {
        float S = 0.f, Q = 0.f;
        #pragma unroll
        for (int i = 0; i < 8; i++) { S += shs[i]; Q += shq[i]; }
        st2[b * 128 + c] = S; st2[b * 128 + 64 + c] = Q;
    }
}

__global__ void k_conv1(const float* __restrict__ x, const float* __restrict__ w,
                        const float* __restrict__ bias, float* __restrict__ y) {
    __shared__ float ws[192], bs[32];
    int t = threadIdx.x;
    if (t < 192) ws[t] = w[t];
    if (t < 32) bs[t] = bias[t];
    __syncthreads();
    int b = blockIdx.y, n = blockIdx.x * 256 + t;
    float in[6];
    #pragma unroll
    for (int c = 0; c < 6; c++) in[c] = x[(b * 6 + c) * NN + n];
    #pragma unroll
    for (int o = 0; o < 32; o++) {
        float a = bs[o];
        #pragma unroll
        for (int c = 0; c < 6; c++) a = fmaf(ws[o * 6 + c], in[c], a);
        y[(b * 32 + o) * NN + n] = a;
    }
}

__global__ void k_bnconv32(const float* __restrict__ yin, const float* __restrict__ st2,
                           const float* __restrict__ g, const float* __restrict__ be,
                           const float* __restrict__ w, const float* __restrict__ bias,
                           float* __restrict__ yout) {
    __shared__ float ws[1024], bs[32], sc[32], sh[32];
    int t = threadIdx.x;
    for (int i = t; i < 1024; i += 256) ws[i] = w[i];
    if (t < 32) { bs[t] = bias[t]; bn_coef8(st2, g, be, t, sc[t], sh[t]); }
    __syncthreads();
    int b = blockIdx.y, n = blockIdx.x * 256 + t;
    float in[32];
    #pragma unroll
    for (int c = 0; c < 32; c++) in[c] = fmaxf(fmaf(sc[c], yin[(b * 32 + c) * NN + n], sh[c]), 0.f);
    for (int o = 0; o < 32; o++) {
        float a = bs[o];
        #pragma unroll
        for (int c = 0; c < 32; c++) a = fmaf(ws[o * 32 + c], in[c], a);
        yout[(b * 32 + o) * NN + n] = a;
    }
}

// BN+relu -> h; q -> fp16 hi/lo planes (n-major); v -> fp16 hi/lo planes (c-major)
template<int C>
__global__ void k_bnqkv(const float* __restrict__ yin, const float* __restrict__ st2,
                        const float* __restrict__ g, const float* __restrict__ be,
                        const float* __restrict__ wqk, const float* __restrict__ wv,
                        const float* __restrict__ bv, float* __restrict__ h,
                        hf* __restrict__ qh, hf* __restrict__ ql,
                        hf* __restrict__ vh, hf* __restrict__ vl) {
    __shared__ float wq_s[C*C], wv_s[C*C], bvs[C], sc[C], sh[C];
    int t = threadIdx.x;
    for (int i = t; i < C*C; i += 256) { wq_s[i] = wqk[i]; wv_s[i] = wv[i]; }
    if (t < C) { bvs[t] = bv[t]; bn_coef8(st2, g, be, t, sc[t], sh[t]); }
    __syncthreads();
    int b = blockIdx.y, n = blockIdx.x * 256 + t;
    float in[C];
    #pragma unroll
    for (int c = 0; c < C; c++) {
        float val = fmaxf(fmaf(sc[c], yin[(b * C + c) * NN + n], sh[c]), 0.f);
        in[c] = val;
        h[(b * C + c) * NN + n] = val;
    }
    size_t qoff = ((size_t)b * NN + n) * C;
    for (int og = 0; og < C; og += 4) {
        uint32_t uh[2], ul[2];
        #pragma unroll
        for (int oo = 0; oo < 4; oo += 2) {
            float q0 = 0.f, q1 = 0.f, av0 = bvs[og+oo], av1 = bvs[og+oo+1];
            #pragma unroll
            for (int c = 0; c < C; c++) {
                q0 = fmaf(wq_s[(og+oo) * C + c], in[c], q0);
                q1 = fmaf(wq_s[(og+oo+1) * C + c], in[c], q1);
                av0 = fmaf(wv_s[(og+oo) * C + c], in[c], av0);
                av1 = fmaf(wv_s[(og+oo+1) * C + c], in[c], av1);
            }
            hf h0 = __float2half_rn(q0), h1 = __float2half_rn(q1);
            uh[oo>>1] = ((uint32_t)__half_as_ushort(h1) << 16) | __half_as_ushort(h0);
            ul[oo>>1] = pk2((q0 - __half2float(h0)) * LSC, (q1 - __half2float(h1)) * LSC);
            hf v0 = __float2half_rn(av0), v1 = __float2half_rn(av1);
            vh[(b * C + og+oo) * NN + n] = v0;
            vh[(b * C + og+oo+1) * NN + n] = v1;
            vl[(b * C + og+oo) * NN + n] = __float2half_rn((av0 - __half2float(v0)) * LSC);
            vl[(b * C + og+oo+1) * NN + n] = __float2half_rn((av1 - __half2float(v1)) * LSC);
        }
        *(uint2*)(qh + qoff + og) = make_uint2(uh[0], uh[1]);
        *(uint2*)(ql + qoff + og) = make_uint2(ul[0], ul[1]);
    }
}

// tile register buffers: ROWS x C halves, both planes
template<int C, int ROWS> struct TR {
    static constexpr int NU = ROWS * C / 8 / 256;
    uint4 h[NU], l[NU];
};
template<int C, int ROWS>
__device__ __forceinline__ void tld(TR<C,ROWS>& tr, const hf* gh, const hf* gl, size_t base, int t) {
    #pragma unroll
    for (int i = 0; i < TR<C,ROWS>::NU; i++) {
        int idx = t + i * 256, row = idx / (C/8), cu = idx % (C/8);
        size_t o = base + (size_t)row * C + cu * 8;
        tr.h[i] = *(const uint4*)(gh + o);
        tr.l[i] = *(const uint4*)(gl + o);
    }
}
template<int C, int ROWS, int S>
__device__ __forceinline__ void tst(const TR<C,ROWS>& tr, hf* sh, hf* sl, int t) {
    #pragma unroll
    for (int i = 0; i < TR<C,ROWS>::NU; i++) {
        int idx = t + i * 256, row = idx / (C/8), cu = idx % (C/8);
        *(uint4*)(sh + row * S + cu * 8) = tr.h[i];
        *(uint4*)(sl + row * S + cu * 8) = tr.l[i];
    }
}
// V tile: C rows x 64 cols from c-major planes (stride NN)
template<int C> struct TRV {
    static constexpr int NU = C * 64 / 8 / 256;
    uint4 h[NU], l[NU];
};
template<int C>
__device__ __forceinline__ void tldv(TRV<C>& tr, const hf* gh, const hf* gl, size_t bC, int n0, int t) {
    #pragma unroll
    for (int i = 0; i < TRV<C>::NU; i++) {
        int idx = t + i * 256, row = idx >> 3, cu = idx & 7;
        size_t o = (bC + row) * NN + n0 + cu * 8;
        tr.h[i] = *(const uint4*)(gh + o);
        tr.l[i] = *(const uint4*)(gl + o);
    }
}
template<int C, int SE>
__device__ __forceinline__ void tstv(const TRV<C>& tr, hf* sh, hf* sl, int t) {
    #pragma unroll
    for (int i = 0; i < TRV<C>::NU; i++) {
        int idx = t + i * 256, row = idx >> 3, cu = idx & 7;
        *(uint4*)(sh + row * SE + cu * 8) = tr.h[i];
        *(uint4*)(sl + row * SE + cu * 8) = tr.l[i];
    }
}

// ---- pass A: S = Qn x Qm^T; per-row online (M, L); prefetched B tiles ----
template<int C>
__global__ void __launch_bounds__(256) k_gramA(const hf* __restrict__ qh, const hf* __restrict__ ql,
                                               float* __restrict__ Mr, float* __restrict__ iLv) {
    constexpr int S = C + 8;
    extern __shared__ float smf[];
    float *RM = smf, *RL = smf + 256;
    hf* Ah = (hf*)(smf + 512);
    hf *Al = Ah + 128*S, *Bh = Al + 128*S, *Bl = Bh + 128*S;
    const int t = threadIdx.x, w = t >> 5, lane = t & 31;
    const int b = blockIdx.y, n0 = blockIdx.x * 128;
    const int rw = (w >> 1) * 32, cw = (w & 1) * 64;
    const int r = lane >> 2, q2 = (lane & 3) * 2;
    const size_t bN = (size_t)b * NN;
    TR<C,128> tr;
    tld<C,128>(tr, qh, ql, (bN + n0) * C, t);
    tst<C,128,S>(tr, Ah, Al, t);
    tld<C,128>(tr, qh, ql, bN * C, t);
    float Mv[4], Lv[4];
    #pragma unroll
    for (int i = 0; i < 4; i++) { Mv[i] = -1e30f; Lv[i] = 0.f; }
    for (int mt = 0; mt < 32; mt++) {
        __syncthreads();
        tst<C,128,S>(tr, Bh, Bl, t);
        __syncthreads();
        if (mt + 1 < 32) tld<C,128>(tr, qh, ql, (bN + (mt + 1) * 128) * C, t);
        float accH[2][8][4], accX[2][8][4];
        #pragma unroll
        for (int rf = 0; rf < 2; rf++)
            #pragma unroll
            for (int j = 0; j < 8; j++)
                #pragma unroll
                for (int e = 0; e < 4; e++) { accH[rf][j][e] = 0.f; accX[rf][j][e] = 0.f; }
        #pragma unroll
        for (int ks = 0; ks < C / 16; ks++) {
            int kb = ks * 16;
            uint32_t ah[2][4], al[2][4];
            #pragma unroll
            for (int rf = 0; rf < 2; rf++) {
                ldfA(ah[rf], Ah, S, rw + rf * 16, kb, r, q2);
                ldfA(al[rf], Al, S, rw + rf * 16, kb, r, q2);
            }
            #pragma unroll
            for (int j = 0; j < 8; j++) {
                int cb = cw + j * 8;
                uint32_t bh0 = *(const uint32_t*)(Bh + (cb + r) * S + kb + q2);
                uint32_t bh1 = *(const uint32_t*)(Bh + (cb + r) * S + kb + q2 + 8);
                uint32_t bl0 = *(const uint32_t*)(Bl + (cb + r) * S + kb + q2);
                uint32_t bl1 = *(const uint32_t*)(Bl + (cb + r) * S + kb + q2 + 8);
                #pragma unroll
                for (int rf = 0; rf < 2; rf++) {
                    mma16(accH[rf][j], ah[rf], bh0, bh1);
                    mma16(accX[rf][j], ah[rf], bl0, bl1);
                    mma16(accX[rf][j], al[rf], bh0, bh1);
                }
            }
        }
        #pragma unroll
        for (int rf = 0; rf < 2; rf++)
            #pragma unroll
            for (int h = 0; h < 2; h++) {
                int i = rf * 2 + h;
                float sv[16];
                #pragma unroll
                for (int j = 0; j < 8; j++) {
                    sv[2*j]   = fmaf(accX[rf][j][2*h],   ILSC, accH[rf][j][2*h]);
                    sv[2*j+1] = fmaf(accX[rf][j][2*h+1], ILSC, accH[rf][j][2*h+1]);
                }
                float tm = -1e30f;
                #pragma unroll
                for (int j = 0; j < 16; j++) tm = fmaxf(tm, sv[j]);
                float Mn = fmaxf(Mv[i], tm);
                float l = Lv[i] * __expf(Mv[i] - Mn);
                #pragma unroll
                for (int j = 0; j < 16; j++) l += __expf(sv[j] - Mn);
                Mv[i] = Mn; Lv[i] = l;
            }
    }
    #pragma unroll
    for (int i = 0; i < 4; i++)
        #pragma unroll
        for (int o = 1; o <= 2; o <<= 1) {
            float M2 = __shfl_xor_sync(~0u, Mv[i], o);
            float L2 = __shfl_xor_sync(~0u, Lv[i], o);
            float Mn = fmaxf(Mv[i], M2);
            Lv[i] = Lv[i] * __expf(Mv[i] - Mn) + L2 * __expf(M2 - Mn);
            Mv[i] = Mn;
        }
    __syncthreads();
    if ((lane & 3) == 0) {
        #pragma unroll
        for (int i = 0; i < 4; i++) {
            int row = rw + (i >> 1) * 16 + (i & 1) * 8 + r;
            RM[row * 2 + (w & 1)] = Mv[i];
            RL[row * 2 + (w & 1)] = Lv[i];
        }
    }
    __syncthreads();
    if (t < 128) {
        float M0 = RM[t*2], M1 = RM[t*2+1], L0 = RL[t*2], L1 = RL[t*2+1];
        float Mn = fmaxf(M0, M1);
        float L = L0 * __expf(M0 - Mn) + L1 * __expf(M1 - Mn);
        Mr[b * NN + n0 + t] = Mn;
        iLv[b * NN + n0 + t] = 1.0f / L;
    }
}

// ---- pass B: S' recompute + exp (E hi+lo) + col sums + xr^T = E x V; prefetched tiles ----
template<int C>
__global__ void __launch_bounds__(256) k_gramB(const hf* __restrict__ qh, const hf* __restrict__ ql,
                                               const hf* __restrict__ vhp, const hf* __restrict__ vlp,
                                               const float* __restrict__ Mr, const float* __restrict__ iLv,
                                               float* __restrict__ xrT) {
    constexpr int S = C + 8, SE = 72, NJ2 = C / 16;
    extern __shared__ float smf[];
    float *Msh = smf, *Lsh = smf + 64, *Red = smf + 128, *Sinv = smf + 384;
    hf* Qmh = (hf*)(smf + 512);
    hf *Qml = Qmh + 128*S, *Qnh = Qml + 128*S, *Qnl = Qnh + 64*S;
    hf *Vh = Qnl + 64*S, *Vl = Vh + C*SE, *Eh = Vl + C*SE, *El = Eh + 128*SE;
    const int t = threadIdx.x, w = t >> 5, lane = t & 31;
    const int b = blockIdx.y, m0 = blockIdx.x * 128;
    const int rw = (w >> 1) * 32, cw = (w & 1) * 32, cw2 = (w & 1) * (C / 2);
    const int r = lane >> 2, q2 = (lane & 3) * 2;
    const size_t bN = (size_t)b * NN, bC = (size_t)b * C;
    {
        TR<C,128> tm_;
        tld<C,128>(tm_, qh, ql, (bN + m0) * C, t);
        tst<C,128,S>(tm_, Qmh, Qml, t);
    }
    TR<C,64> trq;
    TRV<C> trv;
    float pM = 0.f, pL = 0.f;
    tld<C,64>(trq, qh, ql, bN * C, t);
    tldv<C>(trv, vhp, vlp, bC, 0, t);
    if (t < 64) { pM = Mr[b * NN + t]; pL = iLv[b * NN + t]; }
    float acc2H[2][NJ2][4], acc2X[2][NJ2][4];
    #pragma unroll
    for (int rf = 0; rf < 2; rf++)
        #pragma unroll
        for (int j = 0; j < NJ2; j++)
            #pragma unroll
            for (int e = 0; e < 4; e++) { acc2H[rf][j][e] = 0.f; acc2X[rf][j][e] = 0.f; }
    float sacc[4] = {0.f, 0.f, 0.f, 0.f};
    for (int nt = 0; nt < 64; nt++) {
        __syncthreads();
        tst<C,64,S>(trq, Qnh, Qnl, t);
        tstv<C,SE>(trv, Vh, Vl, t);
        if (t < 64) { Msh[t] = pM; Lsh[t] = pL; }
        __syncthreads();
        if (nt + 1 < 64) {
            int n1 = (nt + 1) * 64;
            tld<C,64>(trq, qh, ql, (bN + n1) * C, t);
            tldv<C>(trv, vhp, vlp, bC, n1, t);
            if (t < 64) { pM = Mr[b * NN + n1 + t]; pL = iLv[b * NN + n1 + t]; }
        }
        float accS[2][4][4], accSX[2][4][4];
        #pragma unroll
        for (int rf = 0; rf < 2; rf++)
            #pragma unroll
            for (int j = 0; j < 4; j++)
                #pragma unroll
                for (int e = 0; e < 4; e++) { accS[rf][j][e] = 0.f; accSX[rf][j][e] = 0.f; }
        #pragma unroll
        for (int ks = 0; ks < C / 16; ks++) {
            int kb = ks * 16;
            uint32_t ah[2][4], al[2][4];
            #pragma unroll
            for (int rf = 0; rf < 2; rf++) {
                ldfA(ah[rf], Qmh, S, rw + rf * 16, kb, r, q2);
                ldfA(al[rf], Qml, S, rw + rf * 16, kb, r, q2);
            }
            #pragma unroll
            for (int j = 0; j < 4; j++) {
                int cb = cw + j * 8;
                uint32_t bh0 = *(const uint32_t*)(Qnh + (cb + r) * S + kb + q2);
                uint32_t bh1 = *(const uint32_t*)(Qnh + (cb + r) * S + kb + q2 + 8);
                uint32_t bl0 = *(const uint32_t*)(Qnl + (cb + r) * S + kb + q2);
                uint32_t bl1 = *(const uint32_t*)(Qnl + (cb + r) * S + kb + q2 + 8);
                #pragma unroll
                for (int rf = 0; rf < 2; rf++) {
                    mma16(accS[rf][j], ah[rf], bh0, bh1);
                    mma16(accSX[rf][j], ah[rf], bl0, bl1);
                    mma16(accSX[rf][j], al[rf], bh0, bh1);
                }
            }
        }
        #pragma unroll
        for (int rf = 0; rf < 2; rf++)
            #pragma unroll
            for (int h = 0; h < 2; h++) {
                int row = rw + rf * 16 + h * 8 + r;
                #pragma unroll
                for (int j = 0; j < 4; j++) {
                    int col = cw + j * 8 + q2;
                    float s0 = fmaf(accSX[rf][j][2*h],   ILSC, accS[rf][j][2*h]);
                    float s1 = fmaf(accSX[rf][j][2*h+1], ILSC, accS[rf][j][2*h+1]);
                    float e0 = __expf(s0 - Msh[col])     * Lsh[col];
                    float e1 = __expf(s1 - Msh[col + 1]) * Lsh[col + 1];
                    sacc[rf * 2 + h] += e0 + e1;
                    hf eh0 = __float2half_rn(e0), eh1 = __float2half_rn(e1);
                    *(uint32_t*)(Eh + row * SE + col) =
                        ((uint32_t)__half_as_ushort(eh1) << 16) | __half_as_ushort(eh0);
                    *(uint32_t*)(El + row * SE + col) =
                        pk2((e0 - __half2float(eh0)) * LSC, (e1 - __half2float(eh1)) * LSC);
                }
            }
        __syncthreads();
        #pragma unroll
        for (int ks = 0; ks < 4; ks++) {
            int kb = ks * 16;
            uint32_t ef[2][4], efl[2][4];
            #pragma unroll
            for (int rf = 0; rf < 2; rf++) {
                ldfA(ef[rf], Eh, SE, rw + rf * 16, kb, r, q2);
                ldfA(efl[rf], El, SE, rw + rf * 16, kb, r, q2);
            }
            #pragma unroll
            for (int j = 0; j < NJ2; j++) {
                int cc = cw2 + j * 8;
                uint32_t bh0 = *(const uint32_t*)(Vh + (cc + r) * SE + kb + q2);
                uint32_t bh1 = *(const uint32_t*)(Vh + (cc + r) * SE + kb + q2 + 8);
                uint32_t bl0 = *(const uint32_t*)(Vl + (cc + r) * SE + kb + q2);
                uint32_t bl1 = *(const uint32_t*)(Vl + (cc + r) * SE + kb + q2 + 8);
                #pragma unroll
                for (int rf = 0; rf < 2; rf++) {
                    mma16(acc2H[rf][j], ef[rf], bh0, bh1);
                    mma16(acc2X[rf][j], ef[rf], bl0, bl1);
                    mma16(acc2X[rf][j], efl[rf], bh0, bh1);
                }
            }
        }
    }
    #pragma unroll
    for (int i = 0; i < 4; i++) {
        sacc[i] += __shfl_xor_sync(~0u, sacc[i], 1);
        sacc[i] += __shfl_xor_sync(~0u, sacc[i], 2);
    }
    __syncthreads();
    if ((lane & 3) == 0) {
        #pragma unroll
        for (int i = 0; i < 4; i++) {
            int row = rw + (i >> 1) * 16 + (i & 1) * 8 + r;
            Red[row * 2 + (w & 1)] = sacc[i];
        }
    }
    __syncthreads();
    if (t < 128) Sinv[t] = 1.0f / (1e-9f + Red[t*2] + Red[t*2+1]);
    __syncthreads();
    #pragma unroll
    for (int rf = 0; rf < 2; rf++)
        #pragma unroll
        for (int h = 0; h < 2; h++) {
            int row = rw + rf * 16 + h * 8 + r;
            float si = Sinv[row];
            float* dst = xrT + (bN + m0 + row) * C;
            #pragma unroll
            for (int j = 0; j < NJ2; j++) {
                int col = cw2 + j * 8 + q2;
                float u0 = fmaf(acc2X[rf][j][2*h],   ILSC, acc2H[rf][j][2*h]);
                float u1 = fmaf(acc2X[rf][j][2*h+1], ILSC, acc2H[rf][j][2*h+1]);
                *(float2*)(dst + col) = make_float2(u0 * si, u1 * si);
            }
        }
}

template<int C>
__global__ void k_diffconv(const float* __restrict__ h, const float* __restrict__ xrT,
                           const float* __restrict__ wt, const float* __restrict__ bt,
                           float* __restrict__ tp) {
    __shared__ float ws[C*C], bs[C];
    int t = threadIdx.x;
    for (int i = t; i < C*C; i += 256) ws[i] = wt[i];
    if (t < C) bs[t] = bt[t];
    __syncthreads();
    int b = blockIdx.y, n = blockIdx.x * 256 + t;
    const float* xs = xrT + ((size_t)b * NN + n) * C;
    float din[C];
    #pragma unroll
    for (int c = 0; c < C; c += 4) {
        float4 xv = *(const float4*)(xs + c);
        din[c]     = h[(b * C + c) * NN + n]     - xv.x;
        din[c + 1] = h[(b * C + c + 1) * NN + n] - xv.y;
        din[c + 2] = h[(b * C + c + 2) * NN + n] - xv.z;
        din[c + 3] = h[(b * C + c + 3) * NN + n] - xv.w;
    }
    for (int o = 0; o < C; o++) {
        float a = bs[o];
        #pragma unroll
        for (int c = 0; c < C; c++) a = fmaf(ws[o * C + c], din[c], a);
        tp[(b * C + o) * NN + n] = a;
    }
}

template<int C>
__global__ void k_resid(const float* __restrict__ h, const float* __restrict__ tp,
                        const float* __restrict__ st2, const float* __restrict__ g,
                        const float* __restrict__ be, float* __restrict__ out) {
    __shared__ float scs, shs;
    int idx = blockIdx.x * 256 + threadIdx.x;
    int c = (idx >> 12) & (C - 1);
    if (threadIdx.x == 0) bn_coef8(st2, g, be, c, scs, shs);
    __syncthreads();
    out[idx] = h[idx] + fmaxf(fmaf(scs, tp[idx], shs), 0.f);
}

__global__ void k_max(const float* __restrict__ d, float* __restrict__ gf) {
    int bc = blockIdx.x;
    const float* p = d + bc * NN;
    float m = -1e30f;
    for (int i = threadIdx.x; i < NN; i += 256) m = fmaxf(m, p[i]);
    __shared__ float sm_[8];
    for (int o = 16; o; o >>= 1) m = fmaxf(m, __shfl_down_sync(~0u, m, o));
    if ((threadIdx.x & 31) == 0) sm_[threadIdx.x >> 5] = m;
    __syncthreads();
    if (threadIdx.x == 0) {
        float M = sm_[0];
        #pragma unroll
        for (int i = 1; i < 8; i++) M = fmaxf(M, sm_[i]);
        gf[bc] = M;
    }
}

__global__ void k_concatconv(const float* __restrict__ h3, const float* __restrict__ gf1,
                             const float* __restrict__ w3, const float* __restrict__ b3,
                             float* __restrict__ y3) {
    __shared__ float ws[4096], K[64];
    int t = threadIdx.x, b = blockIdx.y;
    for (int i = t; i < 4096; i += 256) ws[i] = w3[i];
    __syncthreads();
    if (t < 64) {
        float a = b3[t];
        #pragma unroll
        for (int c = 0; c < 32; c++) a = fmaf(ws[t * 64 + 32 + c], gf1[b * 32 + c], a);
        K[t] = a;
    }
    __syncthreads();
    int n = blockIdx.x * 256 + t;
    float in[32];
    #pragma unroll
    for (int c = 0; c < 32; c++) in[c] = h3[(b * 32 + c) * NN + n];
    for (int o = 0; o < 64; o++) {
        float a = K[o];
        #pragma unroll
        for (int c = 0; c < 32; c++) a = fmaf(ws[o * 64 + c], in[c], a);
        y3[(b * 64 + o) * NN + n] = a;
    }
}

extern "C" void kernel_launch(void* const* d_in, const int* in_sizes, int n_in,
                              void* d_out, int out_size) {
    const float *x = (const float*)d_in[0], *w1 = (const float*)d_in[1], *b1 = (const float*)d_in[2],
        *g1 = (const float*)d_in[3], *be1 = (const float*)d_in[4], *w2 = (const float*)d_in[5],
        *b2 = (const float*)d_in[6], *g2 = (const float*)d_in[7], *be2 = (const float*)d_in[8],
        *a1_wqk = (const float*)d_in[9], *a1_wv = (const float*)d_in[10], *a1_bv = (const float*)d_in[11],
        *a1_wt = (const float*)d_in[12], *a1_bt = (const float*)d_in[13], *a1_g = (const float*)d_in[14],
        *a1_b = (const float*)d_in[15], *w3 = (const float*)d_in[16], *b3 = (const float*)d_in[17],
        *g3 = (const float*)d_in[18], *be3 = (const float*)d_in[19], *a2_wqk = (const float*)d_in[20],
        *a2_wv = (const float*)d_in[21], *a2_bv = (const float*)d_in[22], *a2_wt = (const float*)d_in[23],
        *a2_bt = (const float*)d_in[24], *a2_g = (const float*)d_in[25], *a2_b = (const float*)d_in[26];

    float* S = nullptr;
    cudaGetSymbolAddress((void**)&S, SCR);
    float *y1 = S, *y2 = S + BUF, *h2 = S + 2*BUF, *qkB = S + 3*BUF, *vB = S + 4*BUF,
          *xrT = S + 5*BUF, *tpb = S + 6*BUF, *h3 = S + 7*BUF;
    float *Mr = S + 8*BUF, *iL = Mr + BB*NN, *gf1 = iL + BB*NN, *st2 = gf1 + 256 + 5*128;
    hf *qh = (hf*)qkB, *ql = qh + (size_t)BB*NN*64;
    hf *vh = (hf*)vB, *vl = vh + (size_t)BB*NN*64;
    float* outh = (float*)d_out;
    float* outgf = outh + BB * 64 * NN;

    int smA32 = 2048 + 4*128*40*2;
    int smA64 = 2048 + 4*128*72*2;
    int smB32 = 2048 + (2*128*40 + 2*64*40 + 2*32*72 + 2*128*72) * 2;
    int smB64 = 2048 + (2*128*72 + 2*64*72 + 2*64*72 + 2*128*72) * 2;
    cudaFuncSetAttribute(k_gramA<32>, cudaFuncAttributeMaxDynamicSharedMemorySize, smA32);
    cudaFuncSetAttribute(k_gramA<64>, cudaFuncAttributeMaxDynamicSharedMemorySize, smA64);
    cudaFuncSetAttribute(k_gramB<32>, cudaFuncAttributeMaxDynamicSharedMemorySize, smB32);
    cudaFuncSetAttribute(k_gramB<64>, cudaFuncAttributeMaxDynamicSharedMemorySize, smB64);

    dim3 gN(NN / 256, BB), gA(32, BB);
    k_conv1<<<gN, 256>>>(x, w1, b1, y1);
    k_stats1<<<dim3(32, BB), 256>>>(y1, 32, st2);
    k_bnconv32<<<gN, 256>>>(y1, st2, g1, be1, w2, b2, y2);
    k_stats1<<<dim3(32, BB), 256>>>(y2, 32, st2);
    k_bnqkv<32><<<gN, 256>>>(y2, st2, g2, be2, a1_wqk, a1_wv, a1_bv, h2, qh, ql, vh, vl);
    k_gramA<32><<<gA, 256, smA32>>>(qh, ql, Mr, iL);
    k_gramB<32><<<gA, 256, smB32>>>(qh, ql, vh, vl, Mr, iL, xrT);
    k_diffconv<32><<<gN, 256>>>(h2, xrT, a1_wt, a1_bt, tpb);
    k_stats1<<<dim3(32, BB), 256>>>(tpb, 32, st2);
    k_resid<32><<<BB*32*NN/256, 256>>>(h2, tpb, st2, a1_g, a1_b, h3);
    k_max<<<BB * 32, 256>>>(h3, gf1);
    k_concatconv<<<gN, 256>>>(h3, gf1, w3, b3, y2);
    k_stats1<<<dim3(64, BB), 256>>>(y2, 64, st2);
    k_bnqkv<64><<<gN, 256>>>(y2, st2, g3, be3, a2_wqk, a2_wv, a2_bv, y1, qh, ql, vh, vl);
    k_gramA<64><<<gA, 256, smA64>>>(qh, ql, Mr, iL);
    k_gramB<64><<<gA, 256, smB64>>>(qh, ql, vh, vl, Mr, iL, xrT);
    k_diffconv<64><<<gN, 256>>>(y1, xrT, a2_wt, a2_bt, tpb);
    k_stats1<<<dim3(64, BB), 256>>>(tpb, 64, st2);
    k_resid<64><<<BB*64*NN/256, 256>>>(y1, tpb, st2, a2_g, a2_b, outh);
    k_max<<<BB * 64, 256>>>(outh, outgf);
}